// round 1
// baseline (speedup 1.0000x reference)
#include <cuda_runtime.h>
#include <cuda_bf16.h>
#include <math.h>

// ---------------------------------------------------------------------------
// MAB block: B=2, NQ=NKV=2048, D=1024, H=16, DH=64
// tf32 mma.sync GEMMs + flash attention (tf32 QK^T, bf16 PV), fp32 everywhere else
// ---------------------------------------------------------------------------

namespace cfg {
constexpr int BB   = 2;
constexpr int NQC  = 2048;
constexpr int NKVC = 2048;
constexpr int DC   = 1024;
constexpr int DHC  = 64;
constexpr int MR   = BB * NQC;   // 4096 rows
constexpr int DFF  = 4 * DC;     // 4096
}

// scratch (device globals; allocation APIs are forbidden)
__device__ float g_Xn[cfg::MR * cfg::DC];
__device__ float g_Yn[cfg::MR * cfg::DC];
__device__ float g_Qp[cfg::MR * cfg::DC];
__device__ float g_Kp[cfg::MR * cfg::DC];
__device__ float g_Vp[cfg::MR * cfg::DC];
__device__ float g_Hres[cfg::MR * cfg::DC];
__device__ float g_Hr[cfg::MR * cfg::DC];
__device__ float g_Hid[cfg::MR * cfg::DFF];

__device__ __forceinline__ float to_tf32(float x) {
    asm volatile("cvt.rna.tf32.f32 %0, %0;" : "+f"(x));
    return x;
}
__device__ __forceinline__ unsigned fu(float x) { return __float_as_uint(x); }

__device__ __forceinline__ void mma_tf32(float d[4], const unsigned a[4], const unsigned b[2]) {
    asm volatile(
        "mma.sync.aligned.m16n8k8.row.col.f32.tf32.tf32.f32 "
        "{%0,%1,%2,%3},{%4,%5,%6,%7},{%8,%9},{%0,%1,%2,%3};"
        : "+f"(d[0]), "+f"(d[1]), "+f"(d[2]), "+f"(d[3])
        : "r"(a[0]), "r"(a[1]), "r"(a[2]), "r"(a[3]), "r"(b[0]), "r"(b[1]));
}
__device__ __forceinline__ void mma_bf16(float d[4], const unsigned a[4], const unsigned b[2]) {
    asm volatile(
        "mma.sync.aligned.m16n8k16.row.col.f32.bf16.bf16.f32 "
        "{%0,%1,%2,%3},{%4,%5,%6,%7},{%8,%9},{%0,%1,%2,%3};"
        : "+f"(d[0]), "+f"(d[1]), "+f"(d[2]), "+f"(d[3])
        : "r"(a[0]), "r"(a[1]), "r"(a[2]), "r"(a[3]), "r"(b[0]), "r"(b[1]));
}

// ---------------------------------------------------------------------------
// LayerNorm: one block per row, 256 threads, D=1024
// ---------------------------------------------------------------------------
__global__ __launch_bounds__(256) void ln_kernel(const float* __restrict__ x,
                                                 const float* __restrict__ gamma,
                                                 const float* __restrict__ beta,
                                                 float* __restrict__ y) {
    const int row = blockIdx.x;
    const int tid = threadIdx.x;
    const float4 v = reinterpret_cast<const float4*>(x + (size_t)row * cfg::DC)[tid];
    float s  = v.x + v.y + v.z + v.w;
    float sq = v.x * v.x + v.y * v.y + v.z * v.z + v.w * v.w;
#pragma unroll
    for (int o = 16; o; o >>= 1) {
        s  += __shfl_xor_sync(0xffffffffu, s, o);
        sq += __shfl_xor_sync(0xffffffffu, sq, o);
    }
    __shared__ float ssum[8], ssq[8];
    if ((tid & 31) == 0) { ssum[tid >> 5] = s; ssq[tid >> 5] = sq; }
    __syncthreads();
    float ts = 0.f, tq = 0.f;
#pragma unroll
    for (int i = 0; i < 8; i++) { ts += ssum[i]; tq += ssq[i]; }
    const float mu  = ts * (1.f / cfg::DC);
    const float var = tq * (1.f / cfg::DC) - mu * mu;
    const float rs  = rsqrtf(var + 1e-5f);
    const float4 g4 = reinterpret_cast<const float4*>(gamma)[tid];
    const float4 b4 = reinterpret_cast<const float4*>(beta)[tid];
    float4 o;
    o.x = (v.x - mu) * rs * g4.x + b4.x;
    o.y = (v.y - mu) * rs * g4.y + b4.y;
    o.z = (v.z - mu) * rs * g4.z + b4.z;
    o.w = (v.w - mu) * rs * g4.w + b4.w;
    reinterpret_cast<float4*>(y + (size_t)row * cfg::DC)[tid] = o;
}

// ---------------------------------------------------------------------------
// tf32 GEMM: C[M,N] = act(A[M,K] @ W[K,N] + bias) (+ res)
// BM=128 BN=128 BK=32, 256 threads (8 warps, 2x4), warp tile 64x32
// M,N,K all multiples of 128/32 -> no bounds checks.
// ---------------------------------------------------------------------------
__device__ __forceinline__ float gelu_exact(float x) {
    return 0.5f * x * (1.f + erff(x * 0.70710678118654752f));
}

template <bool GELU, bool RES>
__global__ __launch_bounds__(256) void gemm_kernel(const float* __restrict__ A,
                                                   const float* __restrict__ W,
                                                   const float* __restrict__ bias,
                                                   float* __restrict__ C,
                                                   const float* __restrict__ res,
                                                   int M, int N, int K) {
    extern __shared__ float sm[];
    float* As = sm;              // 2 * 128*32
    float* Ws = sm + 2 * 128 * 32;  // 2 * 32*128

    const int tid  = threadIdx.x;
    const int lane = tid & 31;
    const int warp = tid >> 5;
    const int g = lane >> 2, c = lane & 3;
    const int wm = (warp >> 2) * 64;   // 0,64
    const int wn = (warp & 3) * 32;    // 0..96
    const int bm = blockIdx.y * 128;
    const int bn = blockIdx.x * 128;

    const int ar = tid >> 3;           // 0..31 (A tile rows, step 32)
    const int ac = (tid & 7) << 2;     // 0..28
    const int wr = tid >> 5;           // 0..7  (W tile rows, step 8)
    const int wc = (tid & 31) << 2;    // 0..124

    const float* Ag = A + (size_t)(bm + ar) * K + ac;
    const float* Wg = W + (size_t)wr * N + bn + wc;

    float acc[4][4][4];
#pragma unroll
    for (int mt = 0; mt < 4; mt++)
#pragma unroll
        for (int nt = 0; nt < 4; nt++)
#pragma unroll
            for (int i = 0; i < 4; i++) acc[mt][nt][i] = 0.f;

    const int KT = K >> 5;
    float4 abuf[4], wbuf[4];

    // prologue load kt=0
#pragma unroll
    for (int i = 0; i < 4; i++) abuf[i] = *(const float4*)(Ag + (size_t)(i * 32) * K);
#pragma unroll
    for (int i = 0; i < 4; i++) wbuf[i] = *(const float4*)(Wg + (size_t)(i * 8) * N);

    int buf = 0;
    {   // store tile 0
        float* Ab = As;
        float* Wb = Ws;
#pragma unroll
        for (int i = 0; i < 4; i++) {
            const int r = ar + i * 32;
            const int col = ac ^ ((r & 7) << 2);
            float4 v = abuf[i];
            *(float4*)(Ab + r * 32 + col) =
                make_float4(to_tf32(v.x), to_tf32(v.y), to_tf32(v.z), to_tf32(v.w));
        }
#pragma unroll
        for (int i = 0; i < 4; i++) {
            const int r = wr + i * 8;
            const int col = wc ^ ((r & 3) << 3);
            float4 v = wbuf[i];
            *(float4*)(Wb + r * 128 + col) =
                make_float4(to_tf32(v.x), to_tf32(v.y), to_tf32(v.z), to_tf32(v.w));
        }
    }
    __syncthreads();

    for (int kt = 0; kt < KT; kt++) {
        if (kt + 1 < KT) {
            const int k0 = (kt + 1) * 32;
#pragma unroll
            for (int i = 0; i < 4; i++) abuf[i] = *(const float4*)(Ag + (size_t)(i * 32) * K + k0);
#pragma unroll
            for (int i = 0; i < 4; i++) wbuf[i] = *(const float4*)(Wg + (size_t)(k0 + i * 8) * N);
        }
        // compute on buf
        const float* Ab = As + buf * (128 * 32);
        const float* Wb = Ws + buf * (32 * 128);
#pragma unroll
        for (int kk = 0; kk < 4; kk++) {
            const int K0 = kk * 8;
            unsigned bfr[4][2];
#pragma unroll
            for (int nt = 0; nt < 4; nt++) {
                const int n = wn + nt * 8 + g;
                const int swc = n ^ (c << 3);
                bfr[nt][0] = fu(Wb[(K0 + c) * 128 + swc]);
                bfr[nt][1] = fu(Wb[(K0 + c + 4) * 128 + swc]);
            }
            unsigned afr[4][4];
#pragma unroll
            for (int mt = 0; mt < 4; mt++) {
                const int r0 = wm + mt * 16 + g;
                const int cs0 = (K0 + c) ^ (g << 2);
                const int cs1 = (K0 + c + 4) ^ (g << 2);
                afr[mt][0] = fu(Ab[r0 * 32 + cs0]);
                afr[mt][1] = fu(Ab[(r0 + 8) * 32 + cs0]);
                afr[mt][2] = fu(Ab[r0 * 32 + cs1]);
                afr[mt][3] = fu(Ab[(r0 + 8) * 32 + cs1]);
            }
#pragma unroll
            for (int mt = 0; mt < 4; mt++)
#pragma unroll
                for (int nt = 0; nt < 4; nt++) mma_tf32(acc[mt][nt], afr[mt], bfr[nt]);
        }
        if (kt + 1 < KT) {
            float* Ab2 = As + (buf ^ 1) * (128 * 32);
            float* Wb2 = Ws + (buf ^ 1) * (32 * 128);
#pragma unroll
            for (int i = 0; i < 4; i++) {
                const int r = ar + i * 32;
                const int col = ac ^ ((r & 7) << 2);
                float4 v = abuf[i];
                *(float4*)(Ab2 + r * 32 + col) =
                    make_float4(to_tf32(v.x), to_tf32(v.y), to_tf32(v.z), to_tf32(v.w));
            }
#pragma unroll
            for (int i = 0; i < 4; i++) {
                const int r = wr + i * 8;
                const int col = wc ^ ((r & 3) << 3);
                float4 v = wbuf[i];
                *(float4*)(Wb2 + r * 128 + col) =
                    make_float4(to_tf32(v.x), to_tf32(v.y), to_tf32(v.z), to_tf32(v.w));
            }
            __syncthreads();
        }
        buf ^= 1;
    }

    // epilogue
#pragma unroll
    for (int nt = 0; nt < 4; nt++) {
        const int col = bn + wn + nt * 8 + 2 * c;
        const float b0v = bias[col], b1v = bias[col + 1];
#pragma unroll
        for (int mt = 0; mt < 4; mt++) {
            const int r0 = bm + wm + mt * 16 + g;
            float x0 = acc[mt][nt][0] + b0v;
            float x1 = acc[mt][nt][1] + b1v;
            float x2 = acc[mt][nt][2] + b0v;
            float x3 = acc[mt][nt][3] + b1v;
            if (GELU) {
                x0 = gelu_exact(x0); x1 = gelu_exact(x1);
                x2 = gelu_exact(x2); x3 = gelu_exact(x3);
            }
            if (RES) {
                const float2 r0v = *(const float2*)(res + (size_t)r0 * N + col);
                const float2 r1v = *(const float2*)(res + (size_t)(r0 + 8) * N + col);
                x0 += r0v.x; x1 += r0v.y; x2 += r1v.x; x3 += r1v.y;
            }
            *(float2*)(C + (size_t)r0 * N + col)       = make_float2(x0, x1);
            *(float2*)(C + (size_t)(r0 + 8) * N + col) = make_float2(x2, x3);
        }
    }
}

// ---------------------------------------------------------------------------
// Flash attention: grid (NQ/128, H, B), 256 threads (8 warps x 16 query rows)
// S = Q K^T / 32 via tf32 mma; online softmax; P V via bf16 mma (register
// re-pack of S frags into A frags). Null key (idx 2048) = null_k, V = 0.
// Writes Hres = O + X.
// ---------------------------------------------------------------------------
__global__ __launch_bounds__(256) void attn_kernel(const float* __restrict__ Q,
                                                   const float* __restrict__ Kb,
                                                   const float* __restrict__ Vb,
                                                   const float* __restrict__ nk,
                                                   const float* __restrict__ X,
                                                   float* __restrict__ Hres) {
    extern __shared__ char smraw[];
    float* Qs = (float*)smraw;               // 128*64 fp32 (swizzled)
    float* Ks = Qs + 128 * 64;               // 64*64 fp32 (swizzled)
    unsigned* VsT = (unsigned*)(Ks + 64 * 64);  // [dh][keypair] bf16x2, 64*32 u32

    const int b = blockIdx.z, h = blockIdx.y;
    const int q0 = blockIdx.x * 128;
    const int tid = threadIdx.x, lane = tid & 31, warp = tid >> 5;
    const int g = lane >> 2, c = lane & 3;
    const int R0 = warp * 16;
    const int qrowbase = b * cfg::NQC + q0;
    const int hc = h * cfg::DHC;

    // load Q tile (tf32 rounded, swizzled)
    {
        const int r = tid >> 4;
        const int col = (tid & 15) << 2;
#pragma unroll
        for (int i = 0; i < 8; i++) {
            const int rr = r + i * 16;
            float4 v = *(const float4*)(Q + (size_t)(qrowbase + rr) * cfg::DC + hc + col);
            const int sc = col ^ ((rr & 7) << 2);
            *(float4*)(Qs + rr * 64 + sc) =
                make_float4(to_tf32(v.x), to_tf32(v.y), to_tf32(v.z), to_tf32(v.w));
        }
    }

    float m_lo = -1e30f, m_hi = -1e30f;
    float l_lo = 0.f, l_hi = 0.f;
    float o[8][4];
#pragma unroll
    for (int nt = 0; nt < 8; nt++)
#pragma unroll
        for (int i = 0; i < 4; i++) o[nt][i] = 0.f;

    const float scale = 0.03125f;  // 1/sqrt(1024)
    const int NTILES = 33;         // ceil(2049/64)

    for (int kt = 0; kt < NTILES; kt++) {
        const int kb = kt * 64;
        __syncthreads();  // previous tile compute done before overwrite
        {
            const int r = tid >> 4;
            const int col = (tid & 15) << 2;
#pragma unroll
            for (int i = 0; i < 4; i++) {
                const int rr = r + i * 16;
                const int key = kb + rr;
                float4 kv, vv;
                if (key < cfg::NKVC) {
                    kv = *(const float4*)(Kb + (size_t)(b * cfg::NKVC + key) * cfg::DC + hc + col);
                    vv = *(const float4*)(Vb + (size_t)(b * cfg::NKVC + key) * cfg::DC + hc + col);
                } else if (key == cfg::NKVC) {
                    kv = *(const float4*)(nk + hc + col);
                    vv = make_float4(0.f, 0.f, 0.f, 0.f);
                } else {
                    kv = make_float4(0.f, 0.f, 0.f, 0.f);
                    vv = make_float4(0.f, 0.f, 0.f, 0.f);
                }
                const int sc = col ^ ((rr & 7) << 2);
                *(float4*)(Ks + rr * 64 + sc) =
                    make_float4(to_tf32(kv.x), to_tf32(kv.y), to_tf32(kv.z), to_tf32(kv.w));
                const float* vp = &vv.x;
#pragma unroll
                for (int j = 0; j < 4; j++) {
                    const int dh = col + j;
                    const int kp = rr >> 1;
                    const int idx = dh * 32 + (kp ^ ((dh & 7) << 2));
                    __nv_bfloat16* p = ((__nv_bfloat16*)&VsT[idx]) + (rr & 1);
                    *p = __float2bfloat16(vp[j]);
                }
            }
        }
        __syncthreads();

        // S = Q K^T
        float s[8][4];
#pragma unroll
        for (int nt = 0; nt < 8; nt++)
#pragma unroll
            for (int i = 0; i < 4; i++) s[nt][i] = 0.f;
#pragma unroll
        for (int kk = 0; kk < 8; kk++) {
            const int K0 = kk * 8;
            const int cs0 = (K0 + c) ^ (g << 2);
            const int cs1 = (K0 + c + 4) ^ (g << 2);
            unsigned a[4];
            a[0] = fu(Qs[(R0 + g) * 64 + cs0]);
            a[1] = fu(Qs[(R0 + 8 + g) * 64 + cs0]);
            a[2] = fu(Qs[(R0 + g) * 64 + cs1]);
            a[3] = fu(Qs[(R0 + 8 + g) * 64 + cs1]);
#pragma unroll
            for (int nt = 0; nt < 8; nt++) {
                const int key = nt * 8 + g;
                unsigned bb[2];
                bb[0] = fu(Ks[key * 64 + cs0]);
                bb[1] = fu(Ks[key * 64 + cs1]);
                mma_tf32(s[nt], a, bb);
            }
        }
        // scale + mask
#pragma unroll
        for (int nt = 0; nt < 8; nt++)
#pragma unroll
            for (int i = 0; i < 4; i++) s[nt][i] *= scale;
        if (kb + 64 > cfg::NKVC + 1) {
#pragma unroll
            for (int nt = 0; nt < 8; nt++) {
                const int col0 = kb + nt * 8 + 2 * c;
                if (col0 > cfg::NKVC)     { s[nt][0] = -1e30f; s[nt][2] = -1e30f; }
                if (col0 + 1 > cfg::NKVC) { s[nt][1] = -1e30f; s[nt][3] = -1e30f; }
            }
        }
        // row max
        float rmax_lo = -1e30f, rmax_hi = -1e30f;
#pragma unroll
        for (int nt = 0; nt < 8; nt++) {
            rmax_lo = fmaxf(rmax_lo, fmaxf(s[nt][0], s[nt][1]));
            rmax_hi = fmaxf(rmax_hi, fmaxf(s[nt][2], s[nt][3]));
        }
        rmax_lo = fmaxf(rmax_lo, __shfl_xor_sync(0xffffffffu, rmax_lo, 1));
        rmax_lo = fmaxf(rmax_lo, __shfl_xor_sync(0xffffffffu, rmax_lo, 2));
        rmax_hi = fmaxf(rmax_hi, __shfl_xor_sync(0xffffffffu, rmax_hi, 1));
        rmax_hi = fmaxf(rmax_hi, __shfl_xor_sync(0xffffffffu, rmax_hi, 2));
        const float mn_lo = fmaxf(m_lo, rmax_lo);
        const float mn_hi = fmaxf(m_hi, rmax_hi);
        const float alpha_lo = __expf(m_lo - mn_lo);
        const float alpha_hi = __expf(m_hi - mn_hi);
        m_lo = mn_lo; m_hi = mn_hi;

        float rs_lo = 0.f, rs_hi = 0.f;
        unsigned pfrag[4][4];
#pragma unroll
        for (int t = 0; t < 4; t++) {
            const float p00 = __expf(s[2 * t][0] - m_lo);
            const float p01 = __expf(s[2 * t][1] - m_lo);
            const float p10 = __expf(s[2 * t][2] - m_hi);
            const float p11 = __expf(s[2 * t][3] - m_hi);
            const float p20 = __expf(s[2 * t + 1][0] - m_lo);
            const float p21 = __expf(s[2 * t + 1][1] - m_lo);
            const float p30 = __expf(s[2 * t + 1][2] - m_hi);
            const float p31 = __expf(s[2 * t + 1][3] - m_hi);
            rs_lo += p00 + p01 + p20 + p21;
            rs_hi += p10 + p11 + p30 + p31;
            __nv_bfloat162 t0 = __floats2bfloat162_rn(p00, p01);
            __nv_bfloat162 t1 = __floats2bfloat162_rn(p10, p11);
            __nv_bfloat162 t2 = __floats2bfloat162_rn(p20, p21);
            __nv_bfloat162 t3 = __floats2bfloat162_rn(p30, p31);
            pfrag[t][0] = *(unsigned*)&t0;
            pfrag[t][1] = *(unsigned*)&t1;
            pfrag[t][2] = *(unsigned*)&t2;
            pfrag[t][3] = *(unsigned*)&t3;
        }
        rs_lo += __shfl_xor_sync(0xffffffffu, rs_lo, 1);
        rs_lo += __shfl_xor_sync(0xffffffffu, rs_lo, 2);
        rs_hi += __shfl_xor_sync(0xffffffffu, rs_hi, 1);
        rs_hi += __shfl_xor_sync(0xffffffffu, rs_hi, 2);
        l_lo = l_lo * alpha_lo + rs_lo;
        l_hi = l_hi * alpha_hi + rs_hi;
#pragma unroll
        for (int nt = 0; nt < 8; nt++) {
            o[nt][0] *= alpha_lo; o[nt][1] *= alpha_lo;
            o[nt][2] *= alpha_hi; o[nt][3] *= alpha_hi;
        }
        // O += P V  (bf16 mma, k = 16 keys per step)
#pragma unroll
        for (int t = 0; t < 4; t++) {
#pragma unroll
            for (int nt = 0; nt < 8; nt++) {
                const int dh = nt * 8 + g;
                unsigned bb[2];
                bb[0] = VsT[dh * 32 + ((8 * t + c) ^ ((dh & 7) << 2))];
                bb[1] = VsT[dh * 32 + ((8 * t + c + 4) ^ ((dh & 7) << 2))];
                mma_bf16(o[nt], pfrag[t], bb);
            }
        }
    }

    // finalize: Hres = O/l + X
    const float il_lo = 1.f / l_lo;
    const float il_hi = 1.f / l_hi;
    const int row  = qrowbase + R0 + g;
    const int row2 = row + 8;
#pragma unroll
    for (int nt = 0; nt < 8; nt++) {
        const int col = hc + nt * 8 + 2 * c;
        const float2 x0 = *(const float2*)(X + (size_t)row * cfg::DC + col);
        const float2 x1 = *(const float2*)(X + (size_t)row2 * cfg::DC + col);
        *(float2*)(Hres + (size_t)row * cfg::DC + col) =
            make_float2(o[nt][0] * il_lo + x0.x, o[nt][1] * il_lo + x0.y);
        *(float2*)(Hres + (size_t)row2 * cfg::DC + col) =
            make_float2(o[nt][2] * il_hi + x1.x, o[nt][3] * il_hi + x1.y);
    }
}

// ---------------------------------------------------------------------------
extern "C" void kernel_launch(void* const* d_in, const int* in_sizes, int n_in,
                              void* d_out, int out_size) {
    const float* X     = (const float*)d_in[0];
    const float* Y     = (const float*)d_in[1];
    const float* Wq    = (const float*)d_in[2];
    const float* bq    = (const float*)d_in[3];
    const float* Wk    = (const float*)d_in[4];
    const float* bk    = (const float*)d_in[5];
    const float* Wv    = (const float*)d_in[6];
    const float* bv    = (const float*)d_in[7];
    const float* nullk = (const float*)d_in[8];
    const float* g0    = (const float*)d_in[9];
    const float* b0    = (const float*)d_in[10];
    const float* g0kv  = (const float*)d_in[11];
    const float* b0kv  = (const float*)d_in[12];
    const float* g1    = (const float*)d_in[13];
    const float* b1    = (const float*)d_in[14];
    const float* W1    = (const float*)d_in[15];
    const float* bf1   = (const float*)d_in[16];
    const float* W2    = (const float*)d_in[17];
    const float* bf2   = (const float*)d_in[18];
    float* out = (float*)d_out;

    float *Xn, *Yn, *Qp, *Kp, *Vp, *Hres, *Hr, *Hid;
    cudaGetSymbolAddress((void**)&Xn,   g_Xn);
    cudaGetSymbolAddress((void**)&Yn,   g_Yn);
    cudaGetSymbolAddress((void**)&Qp,   g_Qp);
    cudaGetSymbolAddress((void**)&Kp,   g_Kp);
    cudaGetSymbolAddress((void**)&Vp,   g_Vp);
    cudaGetSymbolAddress((void**)&Hres, g_Hres);
    cudaGetSymbolAddress((void**)&Hr,   g_Hr);
    cudaGetSymbolAddress((void**)&Hid,  g_Hid);

    const int gemm_smem = 2 * (128 * 32 + 32 * 128) * (int)sizeof(float);  // 65536
    const int attn_smem = (128 * 64 + 64 * 64) * (int)sizeof(float) + 64 * 32 * 4;  // 57344
    cudaFuncSetAttribute(gemm_kernel<false, false>,
                         cudaFuncAttributeMaxDynamicSharedMemorySize, gemm_smem);
    cudaFuncSetAttribute(gemm_kernel<true, false>,
                         cudaFuncAttributeMaxDynamicSharedMemorySize, gemm_smem);
    cudaFuncSetAttribute(gemm_kernel<false, true>,
                         cudaFuncAttributeMaxDynamicSharedMemorySize, gemm_smem);
    cudaFuncSetAttribute(attn_kernel,
                         cudaFuncAttributeMaxDynamicSharedMemorySize, attn_smem);

    ln_kernel<<<cfg::MR, 256>>>(X, g0, b0, Xn);
    ln_kernel<<<cfg::MR, 256>>>(Y, g0kv, b0kv, Yn);

    gemm_kernel<false, false><<<dim3(cfg::DC / 128, cfg::MR / 128), 256, gemm_smem>>>(
        Xn, Wq, bq, Qp, nullptr, cfg::MR, cfg::DC, cfg::DC);
    gemm_kernel<false, false><<<dim3(cfg::DC / 128, cfg::MR / 128), 256, gemm_smem>>>(
        Yn, Wk, bk, Kp, nullptr, cfg::MR, cfg::DC, cfg::DC);
    gemm_kernel<false, false><<<dim3(cfg::DC / 128, cfg::MR / 128), 256, gemm_smem>>>(
        Yn, Wv, bv, Vp, nullptr, cfg::MR, cfg::DC, cfg::DC);

    attn_kernel<<<dim3(cfg::NQC / 128, 16, cfg::BB), 256, attn_smem>>>(
        Qp, Kp, Vp, nullk, X, Hres);

    ln_kernel<<<cfg::MR, 256>>>(Hres, g1, b1, Hr);

    gemm_kernel<true, false><<<dim3(cfg::DFF / 128, cfg::MR / 128), 256, gemm_smem>>>(
        Hr, W1, bf1, Hid, nullptr, cfg::MR, cfg::DFF, cfg::DC);
    gemm_kernel<false, true><<<dim3(cfg::DC / 128, cfg::MR / 128), 256, gemm_smem>>>(
        Hid, W2, bf2, out, Hres, cfg::MR, cfg::DC, cfg::DFF);
}

// round 3
// speedup vs baseline: 1.0250x; 1.0250x over previous
#include <cuda_runtime.h>
#include <cuda_bf16.h>
#include <cstdint>
#include <math.h>

// ---------------------------------------------------------------------------
// MAB block: B=2, NQ=NKV=2048, D=1024, H=16, DH=64
// tf32 mma.sync GEMMs (cp.async 3-stage, LDS.128 fragments) +
// flash attention (tf32 QK^T, bf16 PV)
// ---------------------------------------------------------------------------

namespace cfg {
constexpr int BB   = 2;
constexpr int NQC  = 2048;
constexpr int NKVC = 2048;
constexpr int DC   = 1024;
constexpr int DHC  = 64;
constexpr int MR   = BB * NQC;   // 4096 rows
constexpr int DFF  = 4 * DC;     // 4096
}

// scratch (device globals; allocation APIs are forbidden)
__device__ float g_Xn[cfg::MR * cfg::DC];
__device__ float g_Yn[cfg::MR * cfg::DC];
__device__ float g_Qp[cfg::MR * cfg::DC];
__device__ float g_Kp[cfg::MR * cfg::DC];
__device__ float g_Vp[cfg::MR * cfg::DC];
__device__ float g_Hres[cfg::MR * cfg::DC];
__device__ float g_Hr[cfg::MR * cfg::DC];
__device__ float g_Hid[cfg::MR * cfg::DFF];
// transposed (and tf32-rounded) weights
__device__ float g_Wqt[cfg::DC * cfg::DC];
__device__ float g_Wkt[cfg::DC * cfg::DC];
__device__ float g_Wvt[cfg::DC * cfg::DC];
__device__ float g_W1t[cfg::DC * cfg::DFF];
__device__ float g_W2t[cfg::DFF * cfg::DC];

__device__ __forceinline__ float to_tf32(float x) {
    asm volatile("cvt.rna.tf32.f32 %0, %0;" : "+f"(x));
    return x;
}
__device__ __forceinline__ unsigned fu(float x) { return __float_as_uint(x); }

__device__ __forceinline__ uint32_t smem_u32(const void* p) {
    uint32_t a;
    asm("{ .reg .u64 t; cvta.to.shared.u64 t, %1; cvt.u32.u64 %0, t; }"
        : "=r"(a) : "l"(p));
    return a;
}

__device__ __forceinline__ void mma_tf32(float d[4], const unsigned a[4], const unsigned b[2]) {
    asm volatile(
        "mma.sync.aligned.m16n8k8.row.col.f32.tf32.tf32.f32 "
        "{%0,%1,%2,%3},{%4,%5,%6,%7},{%8,%9},{%0,%1,%2,%3};"
        : "+f"(d[0]), "+f"(d[1]), "+f"(d[2]), "+f"(d[3])
        : "r"(a[0]), "r"(a[1]), "r"(a[2]), "r"(a[3]), "r"(b[0]), "r"(b[1]));
}
__device__ __forceinline__ void mma_bf16(float d[4], const unsigned a[4], const unsigned b[2]) {
    asm volatile(
        "mma.sync.aligned.m16n8k16.row.col.f32.bf16.bf16.f32 "
        "{%0,%1,%2,%3},{%4,%5,%6,%7},{%8,%9},{%0,%1,%2,%3};"
        : "+f"(d[0]), "+f"(d[1]), "+f"(d[2]), "+f"(d[3])
        : "r"(a[0]), "r"(a[1]), "r"(a[2]), "r"(a[3]), "r"(b[0]), "r"(b[1]));
}

__device__ __forceinline__ void cp_async16(uint32_t smem_addr, const void* gptr) {
    asm volatile("cp.async.cg.shared.global [%0], [%1], 16;\n"
                 :: "r"(smem_addr), "l"(gptr));
}
__device__ __forceinline__ void cp_commit() {
    asm volatile("cp.async.commit_group;\n" ::: "memory");
}
template <int N>
__device__ __forceinline__ void cp_wait() {
    asm volatile("cp.async.wait_group %0;\n" :: "n"(N) : "memory");
}

// ---------------------------------------------------------------------------
// LayerNorm: one block per row, 256 threads, D=1024. Output rounded to tf32
// (all LN outputs feed tf32 GEMM A operands).
// ---------------------------------------------------------------------------
__global__ __launch_bounds__(256) void ln_kernel(const float* __restrict__ x,
                                                 const float* __restrict__ gamma,
                                                 const float* __restrict__ beta,
                                                 float* __restrict__ y) {
    const int row = blockIdx.x;
    const int tid = threadIdx.x;
    const float4 v = reinterpret_cast<const float4*>(x + (size_t)row * cfg::DC)[tid];
    float s  = v.x + v.y + v.z + v.w;
    float sq = v.x * v.x + v.y * v.y + v.z * v.z + v.w * v.w;
#pragma unroll
    for (int o = 16; o; o >>= 1) {
        s  += __shfl_xor_sync(0xffffffffu, s, o);
        sq += __shfl_xor_sync(0xffffffffu, sq, o);
    }
    __shared__ float ssum[8], ssq[8];
    if ((tid & 31) == 0) { ssum[tid >> 5] = s; ssq[tid >> 5] = sq; }
    __syncthreads();
    float ts = 0.f, tq = 0.f;
#pragma unroll
    for (int i = 0; i < 8; i++) { ts += ssum[i]; tq += ssq[i]; }
    const float mu  = ts * (1.f / cfg::DC);
    const float var = tq * (1.f / cfg::DC) - mu * mu;
    const float rs  = rsqrtf(var + 1e-5f);
    const float4 g4 = reinterpret_cast<const float4*>(gamma)[tid];
    const float4 b4 = reinterpret_cast<const float4*>(beta)[tid];
    float4 o;
    o.x = to_tf32((v.x - mu) * rs * g4.x + b4.x);
    o.y = to_tf32((v.y - mu) * rs * g4.y + b4.y);
    o.z = to_tf32((v.z - mu) * rs * g4.z + b4.z);
    o.w = to_tf32((v.w - mu) * rs * g4.w + b4.w);
    reinterpret_cast<float4*>(y + (size_t)row * cfg::DC)[tid] = o;
}

// ---------------------------------------------------------------------------
// Weight transpose: W[K][N] -> Wt[N][K], rounded to tf32.
// ---------------------------------------------------------------------------
__global__ __launch_bounds__(256) void transpose_kernel(const float* __restrict__ W,
                                                        float* __restrict__ Wt,
                                                        int K, int N) {
    __shared__ float t[32][33];
    const int k0 = blockIdx.y * 32, n0 = blockIdx.x * 32;
    const int tx = threadIdx.x & 31, ty = threadIdx.x >> 5;  // 32 x 8
#pragma unroll
    for (int j = 0; j < 4; j++)
        t[ty + j * 8][tx] = W[(size_t)(k0 + ty + j * 8) * N + n0 + tx];
    __syncthreads();
#pragma unroll
    for (int j = 0; j < 4; j++)
        Wt[(size_t)(n0 + ty + j * 8) * K + k0 + tx] = to_tf32(t[tx][ty + j * 8]);
}

// ---------------------------------------------------------------------------
// tf32 GEMM v2: C[M,N] = act(A[M,K] @ Wt[N,K]^T + bias) (+ res)
// BM=128 BN=128 BK=32, 256 threads (8 warps 2x4), warp tile 64x32.
// cp.async 3-stage pipeline; all fragment loads are LDS.128 via the
// k-permutation trick (mma m's k-slots live at smem floats c*8 + 2m + s).
// Inputs must be pre-rounded to tf32 (producers handle this).
// ---------------------------------------------------------------------------
__device__ __forceinline__ float gelu_exact(float x) {
    return 0.5f * x * (1.f + erff(x * 0.70710678118654752f));
}

constexpr int STAGES = 3;

#define EL(v, i) (((const float*)&(v))[i])

template <bool GELU, bool RES>
__global__ __launch_bounds__(256) void gemm2_kernel(const float* __restrict__ A,
                                                    const float* __restrict__ Wt,
                                                    const float* __restrict__ bias,
                                                    float* __restrict__ C,
                                                    const float* __restrict__ res,
                                                    int M, int N, int K) {
    extern __shared__ float sm[];
    float* As = sm;                        // [STAGES][128*32]
    float* Bs = sm + STAGES * 128 * 32;    // [STAGES][128*32]  (n-major)

    const int tid  = threadIdx.x;
    const int lane = tid & 31;
    const int warp = tid >> 5;
    const int g = lane >> 2, c = lane & 3;
    const int wm = (warp >> 2) * 64;   // 0,64
    const int wn = (warp & 3) * 32;    // 0..96
    const int bm = blockIdx.y * 128;
    const int bn = blockIdx.x * 128;

    // cp.async assignment: 2 threads per row, 4 chunks (16B) each
    const int lrow = tid >> 1;           // 0..127
    const int lch0 = (tid & 1) * 4;      // 0 or 4
    const float* Ag = A  + (size_t)(bm + lrow) * K + lch0 * 4;
    const float* Bg = Wt + (size_t)(bn + lrow) * K + lch0 * 4;

    const uint32_t a_smem = smem_u32(As) + (uint32_t)(lrow * 128);
    const uint32_t b_smem = smem_u32(Bs) + (uint32_t)(lrow * 128);
    uint32_t dstoff[4];
#pragma unroll
    for (int j = 0; j < 4; j++) dstoff[j] = (uint32_t)(((lch0 + j) ^ (lrow & 7)) * 16);

    float acc[4][4][4];
#pragma unroll
    for (int mt = 0; mt < 4; mt++)
#pragma unroll
        for (int nt = 0; nt < 4; nt++)
#pragma unroll
            for (int i = 0; i < 4; i++) acc[mt][nt][i] = 0.f;

    const int KT = K >> 5;

    // prologue: fill STAGES-1 stages
#pragma unroll
    for (int s = 0; s < STAGES - 1; s++) {
        const float* ag = Ag + s * 32;
        const float* bg = Bg + s * 32;
#pragma unroll
        for (int j = 0; j < 4; j++)
            cp_async16(a_smem + s * 16384 + dstoff[j], ag + j * 4);
#pragma unroll
        for (int j = 0; j < 4; j++)
            cp_async16(b_smem + s * 16384 + dstoff[j], bg + j * 4);
        cp_commit();
    }

    const int ch0 = ((2 * c) ^ g) * 4;       // phys float offset of logical chunk 2c
    const int ch1 = ((2 * c + 1) ^ g) * 4;

    for (int kt = 0; kt < KT; kt++) {
        cp_wait<STAGES - 2>();
        __syncthreads();

        const int ktn = kt + STAGES - 1;
        if (ktn < KT) {
            const int s = ktn % STAGES;
            const float* ag = Ag + ktn * 32;
            const float* bg = Bg + ktn * 32;
#pragma unroll
            for (int j = 0; j < 4; j++)
                cp_async16(a_smem + s * 16384 + dstoff[j], ag + j * 4);
#pragma unroll
            for (int j = 0; j < 4; j++)
                cp_async16(b_smem + s * 16384 + dstoff[j], bg + j * 4);
        }
        cp_commit();

        const float* Ab = As + (kt % STAGES) * 4096;
        const float* Bb = Bs + (kt % STAGES) * 4096;

        float4 bf0[4], bf1[4];
#pragma unroll
        for (int nt = 0; nt < 4; nt++) {
            const float* bp = Bb + (wn + nt * 8 + g) * 32;
            bf0[nt] = *(const float4*)(bp + ch0);
            bf1[nt] = *(const float4*)(bp + ch1);
        }
#pragma unroll
        for (int mt = 0; mt < 4; mt++) {
            const float* ap  = Ab + (wm + mt * 16 + g) * 32;
            const float* ap2 = ap + 8 * 32;
            const float4 a00 = *(const float4*)(ap + ch0);
            const float4 a01 = *(const float4*)(ap + ch1);
            const float4 a10 = *(const float4*)(ap2 + ch0);
            const float4 a11 = *(const float4*)(ap2 + ch1);
#pragma unroll
            for (int m = 0; m < 4; m++) {
                const int e = 2 * (m & 1);
                const float4& al = (m < 2) ? a00 : a01;
                const float4& ah = (m < 2) ? a10 : a11;
                unsigned afr[4] = { fu(EL(al, e)), fu(EL(ah, e)),
                                    fu(EL(al, e + 1)), fu(EL(ah, e + 1)) };
#pragma unroll
                for (int nt = 0; nt < 4; nt++) {
                    const float4& bl = (m < 2) ? bf0[nt] : bf1[nt];
                    unsigned bfr[2] = { fu(EL(bl, e)), fu(EL(bl, e + 1)) };
                    mma_tf32(acc[mt][nt], afr, bfr);
                }
            }
        }
        __syncthreads();
    }

    // epilogue
#pragma unroll
    for (int nt = 0; nt < 4; nt++) {
        const int col = bn + wn + nt * 8 + 2 * c;
        const float b0v = bias[col], b1v = bias[col + 1];
#pragma unroll
        for (int mt = 0; mt < 4; mt++) {
            const int r0 = bm + wm + mt * 16 + g;
            float x0 = acc[mt][nt][0] + b0v;
            float x1 = acc[mt][nt][1] + b1v;
            float x2 = acc[mt][nt][2] + b0v;
            float x3 = acc[mt][nt][3] + b1v;
            if (GELU) {
                x0 = to_tf32(gelu_exact(x0)); x1 = to_tf32(gelu_exact(x1));
                x2 = to_tf32(gelu_exact(x2)); x3 = to_tf32(gelu_exact(x3));
            }
            if (RES) {
                const float2 r0v = *(const float2*)(res + (size_t)r0 * N + col);
                const float2 r1v = *(const float2*)(res + (size_t)(r0 + 8) * N + col);
                x0 += r0v.x; x1 += r0v.y; x2 += r1v.x; x3 += r1v.y;
            }
            *(float2*)(C + (size_t)r0 * N + col)       = make_float2(x0, x1);
            *(float2*)(C + (size_t)(r0 + 8) * N + col) = make_float2(x2, x3);
        }
    }
}

// ---------------------------------------------------------------------------
// Flash attention: grid (NQ/128, H, B), 256 threads (8 warps x 16 query rows)
// ---------------------------------------------------------------------------
__global__ __launch_bounds__(256) void attn_kernel(const float* __restrict__ Q,
                                                   const float* __restrict__ Kb,
                                                   const float* __restrict__ Vb,
                                                   const float* __restrict__ nk,
                                                   const float* __restrict__ X,
                                                   float* __restrict__ Hres) {
    extern __shared__ char smraw[];
    float* Qs = (float*)smraw;               // 128*64 fp32 (swizzled)
    float* Ks = Qs + 128 * 64;               // 64*64 fp32 (swizzled)
    unsigned* VsT = (unsigned*)(Ks + 64 * 64);  // [dh][keypair] bf16x2, 64*32 u32

    const int b = blockIdx.z, h = blockIdx.y;
    const int q0 = blockIdx.x * 128;
    const int tid = threadIdx.x, lane = tid & 31, warp = tid >> 5;
    const int g = lane >> 2, c = lane & 3;
    const int R0 = warp * 16;
    const int qrowbase = b * cfg::NQC + q0;
    const int hc = h * cfg::DHC;

    {
        const int r = tid >> 4;
        const int col = (tid & 15) << 2;
#pragma unroll
        for (int i = 0; i < 8; i++) {
            const int rr = r + i * 16;
            float4 v = *(const float4*)(Q + (size_t)(qrowbase + rr) * cfg::DC + hc + col);
            const int sc = col ^ ((rr & 7) << 2);
            *(float4*)(Qs + rr * 64 + sc) =
                make_float4(to_tf32(v.x), to_tf32(v.y), to_tf32(v.z), to_tf32(v.w));
        }
    }

    float m_lo = -1e30f, m_hi = -1e30f;
    float l_lo = 0.f, l_hi = 0.f;
    float o[8][4];
#pragma unroll
    for (int nt = 0; nt < 8; nt++)
#pragma unroll
        for (int i = 0; i < 4; i++) o[nt][i] = 0.f;

    const float scale = 0.03125f;  // 1/sqrt(1024)
    const int NTILES = 33;         // ceil(2049/64)

    for (int kt = 0; kt < NTILES; kt++) {
        const int kb = kt * 64;
        __syncthreads();
        {
            const int r = tid >> 4;
            const int col = (tid & 15) << 2;
#pragma unroll
            for (int i = 0; i < 4; i++) {
                const int rr = r + i * 16;
                const int key = kb + rr;
                float4 kv, vv;
                if (key < cfg::NKVC) {
                    kv = *(const float4*)(Kb + (size_t)(b * cfg::NKVC + key) * cfg::DC + hc + col);
                    vv = *(const float4*)(Vb + (size_t)(b * cfg::NKVC + key) * cfg::DC + hc + col);
                } else if (key == cfg::NKVC) {
                    kv = *(const float4*)(nk + hc + col);
                    vv = make_float4(0.f, 0.f, 0.f, 0.f);
                } else {
                    kv = make_float4(0.f, 0.f, 0.f, 0.f);
                    vv = make_float4(0.f, 0.f, 0.f, 0.f);
                }
                const int sc = col ^ ((rr & 7) << 2);
                *(float4*)(Ks + rr * 64 + sc) =
                    make_float4(to_tf32(kv.x), to_tf32(kv.y), to_tf32(kv.z), to_tf32(kv.w));
                const float* vp = &vv.x;
#pragma unroll
                for (int j = 0; j < 4; j++) {
                    const int dh = col + j;
                    const int kp = rr >> 1;
                    const int idx = dh * 32 + (kp ^ ((dh & 7) << 2));
                    __nv_bfloat16* p = ((__nv_bfloat16*)&VsT[idx]) + (rr & 1);
                    *p = __float2bfloat16(vp[j]);
                }
            }
        }
        __syncthreads();

        float s[8][4];
#pragma unroll
        for (int nt = 0; nt < 8; nt++)
#pragma unroll
            for (int i = 0; i < 4; i++) s[nt][i] = 0.f;
#pragma unroll
        for (int kk = 0; kk < 8; kk++) {
            const int K0 = kk * 8;
            const int cs0 = (K0 + c) ^ (g << 2);
            const int cs1 = (K0 + c + 4) ^ (g << 2);
            unsigned a[4];
            a[0] = fu(Qs[(R0 + g) * 64 + cs0]);
            a[1] = fu(Qs[(R0 + 8 + g) * 64 + cs0]);
            a[2] = fu(Qs[(R0 + g) * 64 + cs1]);
            a[3] = fu(Qs[(R0 + 8 + g) * 64 + cs1]);
#pragma unroll
            for (int nt = 0; nt < 8; nt++) {
                const int key = nt * 8 + g;
                unsigned bb[2];
                bb[0] = fu(Ks[key * 64 + cs0]);
                bb[1] = fu(Ks[key * 64 + cs1]);
                mma_tf32(s[nt], a, bb);
            }
        }
#pragma unroll
        for (int nt = 0; nt < 8; nt++)
#pragma unroll
            for (int i = 0; i < 4; i++) s[nt][i] *= scale;
        if (kb + 64 > cfg::NKVC + 1) {
#pragma unroll
            for (int nt = 0; nt < 8; nt++) {
                const int col0 = kb + nt * 8 + 2 * c;
                if (col0 > cfg::NKVC)     { s[nt][0] = -1e30f; s[nt][2] = -1e30f; }
                if (col0 + 1 > cfg::NKVC) { s[nt][1] = -1e30f; s[nt][3] = -1e30f; }
            }
        }
        float rmax_lo = -1e30f, rmax_hi = -1e30f;
#pragma unroll
        for (int nt = 0; nt < 8; nt++) {
            rmax_lo = fmaxf(rmax_lo, fmaxf(s[nt][0], s[nt][1]));
            rmax_hi = fmaxf(rmax_hi, fmaxf(s[nt][2], s[nt][3]));
        }
        rmax_lo = fmaxf(rmax_lo, __shfl_xor_sync(0xffffffffu, rmax_lo, 1));
        rmax_lo = fmaxf(rmax_lo, __shfl_xor_sync(0xffffffffu, rmax_lo, 2));
        rmax_hi = fmaxf(rmax_hi, __shfl_xor_sync(0xffffffffu, rmax_hi, 1));
        rmax_hi = fmaxf(rmax_hi, __shfl_xor_sync(0xffffffffu, rmax_hi, 2));
        const float mn_lo = fmaxf(m_lo, rmax_lo);
        const float mn_hi = fmaxf(m_hi, rmax_hi);
        const float alpha_lo = __expf(m_lo - mn_lo);
        const float alpha_hi = __expf(m_hi - mn_hi);
        m_lo = mn_lo; m_hi = mn_hi;

        float rs_lo = 0.f, rs_hi = 0.f;
        unsigned pfrag[4][4];
#pragma unroll
        for (int t = 0; t < 4; t++) {
            const float p00 = __expf(s[2 * t][0] - m_lo);
            const float p01 = __expf(s[2 * t][1] - m_lo);
            const float p10 = __expf(s[2 * t][2] - m_hi);
            const float p11 = __expf(s[2 * t][3] - m_hi);
            const float p20 = __expf(s[2 * t + 1][0] - m_lo);
            const float p21 = __expf(s[2 * t + 1][1] - m_lo);
            const float p30 = __expf(s[2 * t + 1][2] - m_hi);
            const float p31 = __expf(s[2 * t + 1][3] - m_hi);
            rs_lo += p00 + p01 + p20 + p21;
            rs_hi += p10 + p11 + p30 + p31;
            __nv_bfloat162 t0 = __floats2bfloat162_rn(p00, p01);
            __nv_bfloat162 t1 = __floats2bfloat162_rn(p10, p11);
            __nv_bfloat162 t2 = __floats2bfloat162_rn(p20, p21);
            __nv_bfloat162 t3 = __floats2bfloat162_rn(p30, p31);
            pfrag[t][0] = *(unsigned*)&t0;
            pfrag[t][1] = *(unsigned*)&t1;
            pfrag[t][2] = *(unsigned*)&t2;
            pfrag[t][3] = *(unsigned*)&t3;
        }
        rs_lo += __shfl_xor_sync(0xffffffffu, rs_lo, 1);
        rs_lo += __shfl_xor_sync(0xffffffffu, rs_lo, 2);
        rs_hi += __shfl_xor_sync(0xffffffffu, rs_hi, 1);
        rs_hi += __shfl_xor_sync(0xffffffffu, rs_hi, 2);
        l_lo = l_lo * alpha_lo + rs_lo;
        l_hi = l_hi * alpha_hi + rs_hi;
#pragma unroll
        for (int nt = 0; nt < 8; nt++) {
            o[nt][0] *= alpha_lo; o[nt][1] *= alpha_lo;
            o[nt][2] *= alpha_hi; o[nt][3] *= alpha_hi;
        }
#pragma unroll
        for (int t = 0; t < 4; t++) {
#pragma unroll
            for (int nt = 0; nt < 8; nt++) {
                const int dh = nt * 8 + g;
                unsigned bb[2];
                bb[0] = VsT[dh * 32 + ((8 * t + c) ^ ((dh & 7) << 2))];
                bb[1] = VsT[dh * 32 + ((8 * t + c + 4) ^ ((dh & 7) << 2))];
                mma_bf16(o[nt], pfrag[t], bb);
            }
        }
    }

    const float il_lo = 1.f / l_lo;
    const float il_hi = 1.f / l_hi;
    const int row  = qrowbase + R0 + g;
    const int row2 = row + 8;
#pragma unroll
    for (int nt = 0; nt < 8; nt++) {
        const int col = hc + nt * 8 + 2 * c;
        const float2 x0 = *(const float2*)(X + (size_t)row * cfg::DC + col);
        const float2 x1 = *(const float2*)(X + (size_t)row2 * cfg::DC + col);
        *(float2*)(Hres + (size_t)row * cfg::DC + col) =
            make_float2(o[nt][0] * il_lo + x0.x, o[nt][1] * il_lo + x0.y);
        *(float2*)(Hres + (size_t)row2 * cfg::DC + col) =
            make_float2(o[nt][2] * il_hi + x1.x, o[nt][3] * il_hi + x1.y);
    }
}

// ---------------------------------------------------------------------------
extern "C" void kernel_launch(void* const* d_in, const int* in_sizes, int n_in,
                              void* d_out, int out_size) {
    const float* X     = (const float*)d_in[0];
    const float* Y     = (const float*)d_in[1];
    const float* Wq    = (const float*)d_in[2];
    const float* bq    = (const float*)d_in[3];
    const float* Wk    = (const float*)d_in[4];
    const float* bk    = (const float*)d_in[5];
    const float* Wv    = (const float*)d_in[6];
    const float* bv    = (const float*)d_in[7];
    const float* nullk = (const float*)d_in[8];
    const float* g0    = (const float*)d_in[9];
    const float* b0    = (const float*)d_in[10];
    const float* g0kv  = (const float*)d_in[11];
    const float* b0kv  = (const float*)d_in[12];
    const float* g1    = (const float*)d_in[13];
    const float* b1    = (const float*)d_in[14];
    const float* W1    = (const float*)d_in[15];
    const float* bf1   = (const float*)d_in[16];
    const float* W2    = (const float*)d_in[17];
    const float* bf2   = (const float*)d_in[18];
    float* out = (float*)d_out;

    float *Xn, *Yn, *Qp, *Kp, *Vp, *Hres, *Hr, *Hid;
    float *Wqt, *Wkt, *Wvt, *W1t, *W2t;
    cudaGetSymbolAddress((void**)&Xn,   g_Xn);
    cudaGetSymbolAddress((void**)&Yn,   g_Yn);
    cudaGetSymbolAddress((void**)&Qp,   g_Qp);
    cudaGetSymbolAddress((void**)&Kp,   g_Kp);
    cudaGetSymbolAddress((void**)&Vp,   g_Vp);
    cudaGetSymbolAddress((void**)&Hres, g_Hres);
    cudaGetSymbolAddress((void**)&Hr,   g_Hr);
    cudaGetSymbolAddress((void**)&Hid,  g_Hid);
    cudaGetSymbolAddress((void**)&Wqt,  g_Wqt);
    cudaGetSymbolAddress((void**)&Wkt,  g_Wkt);
    cudaGetSymbolAddress((void**)&Wvt,  g_Wvt);
    cudaGetSymbolAddress((void**)&W1t,  g_W1t);
    cudaGetSymbolAddress((void**)&W2t,  g_W2t);

    const int gemm_smem = STAGES * (128 * 32 + 128 * 32) * (int)sizeof(float);  // 98304
    const int attn_smem = (128 * 64 + 64 * 64) * (int)sizeof(float) + 64 * 32 * 4;  // 57344
    cudaFuncSetAttribute(gemm2_kernel<false, false>,
                         cudaFuncAttributeMaxDynamicSharedMemorySize, gemm_smem);
    cudaFuncSetAttribute(gemm2_kernel<true, false>,
                         cudaFuncAttributeMaxDynamicSharedMemorySize, gemm_smem);
    cudaFuncSetAttribute(gemm2_kernel<false, true>,
                         cudaFuncAttributeMaxDynamicSharedMemorySize, gemm_smem);
    cudaFuncSetAttribute(attn_kernel,
                         cudaFuncAttributeMaxDynamicSharedMemorySize, attn_smem);

    // weight transposes (+ tf32 rounding)
    transpose_kernel<<<dim3(cfg::DC / 32, cfg::DC / 32), 256>>>(Wq, Wqt, cfg::DC, cfg::DC);
    transpose_kernel<<<dim3(cfg::DC / 32, cfg::DC / 32), 256>>>(Wk, Wkt, cfg::DC, cfg::DC);
    transpose_kernel<<<dim3(cfg::DC / 32, cfg::DC / 32), 256>>>(Wv, Wvt, cfg::DC, cfg::DC);
    transpose_kernel<<<dim3(cfg::DFF / 32, cfg::DC / 32), 256>>>(W1, W1t, cfg::DC, cfg::DFF);
    transpose_kernel<<<dim3(cfg::DC / 32, cfg::DFF / 32), 256>>>(W2, W2t, cfg::DFF, cfg::DC);

    ln_kernel<<<cfg::MR, 256>>>(X, g0, b0, Xn);
    ln_kernel<<<cfg::MR, 256>>>(Y, g0kv, b0kv, Yn);

    gemm2_kernel<false, false><<<dim3(cfg::DC / 128, cfg::MR / 128), 256, gemm_smem>>>(
        Xn, Wqt, bq, Qp, nullptr, cfg::MR, cfg::DC, cfg::DC);
    gemm2_kernel<false, false><<<dim3(cfg::DC / 128, cfg::MR / 128), 256, gemm_smem>>>(
        Yn, Wkt, bk, Kp, nullptr, cfg::MR, cfg::DC, cfg::DC);
    gemm2_kernel<false, false><<<dim3(cfg::DC / 128, cfg::MR / 128), 256, gemm_smem>>>(
        Yn, Wvt, bv, Vp, nullptr, cfg::MR, cfg::DC, cfg::DC);

    attn_kernel<<<dim3(cfg::NQC / 128, 16, cfg::BB), 256, attn_smem>>>(
        Qp, Kp, Vp, nullk, X, Hres);

    ln_kernel<<<cfg::MR, 256>>>(Hres, g1, b1, Hr);

    gemm2_kernel<true, false><<<dim3(cfg::DFF / 128, cfg::MR / 128), 256, gemm_smem>>>(
        Hr, W1t, bf1, Hid, nullptr, cfg::MR, cfg::DFF, cfg::DC);
    gemm2_kernel<false, true><<<dim3(cfg::DC / 128, cfg::MR / 128), 256, gemm_smem>>>(
        Hid, W2t, bf2, out, Hres, cfg::MR, cfg::DC, cfg::DFF);
}

// round 4
// speedup vs baseline: 1.0658x; 1.0398x over previous
#include <cuda_runtime.h>
#include <cuda_bf16.h>
#include <cstdint>
#include <math.h>

// ---------------------------------------------------------------------------
// MAB block: B=2, NQ=NKV=2048, D=1024, H=16, DH=64
// tf32 mma.sync GEMMs (cp.async 3-stage, 1 sync/iter, 2 CTA/SM) +
// flash attention (tf32 QK^T, bf16 PV)
// ---------------------------------------------------------------------------

namespace cfg {
constexpr int BB   = 2;
constexpr int NQC  = 2048;
constexpr int NKVC = 2048;
constexpr int DC   = 1024;
constexpr int DHC  = 64;
constexpr int MR   = BB * NQC;   // 4096 rows
constexpr int DFF  = 4 * DC;     // 4096
}

// scratch (device globals; allocation APIs are forbidden)
__device__ float g_Xn[cfg::MR * cfg::DC];
__device__ float g_Yn[cfg::MR * cfg::DC];
__device__ float g_Qp[cfg::MR * cfg::DC];
__device__ float g_Kp[cfg::MR * cfg::DC];
__device__ float g_Vp[cfg::MR * cfg::DC];
__device__ float g_Hres[cfg::MR * cfg::DC];
__device__ float g_Hr[cfg::MR * cfg::DC];
__device__ float g_Hid[cfg::MR * cfg::DFF];
// transposed (and tf32-rounded) weights
__device__ float g_Wqt[cfg::DC * cfg::DC];
__device__ float g_Wkt[cfg::DC * cfg::DC];
__device__ float g_Wvt[cfg::DC * cfg::DC];
__device__ float g_W1t[cfg::DC * cfg::DFF];
__device__ float g_W2t[cfg::DFF * cfg::DC];

__device__ __forceinline__ float to_tf32(float x) {
    asm volatile("cvt.rna.tf32.f32 %0, %0;" : "+f"(x));
    return x;
}
__device__ __forceinline__ unsigned fu(float x) { return __float_as_uint(x); }

__device__ __forceinline__ uint32_t smem_u32(const void* p) {
    uint32_t a;
    asm("{ .reg .u64 t; cvta.to.shared.u64 t, %1; cvt.u32.u64 %0, t; }"
        : "=r"(a) : "l"(p));
    return a;
}

__device__ __forceinline__ void mma_tf32(float d[4], const unsigned a[4], const unsigned b[2]) {
    asm volatile(
        "mma.sync.aligned.m16n8k8.row.col.f32.tf32.tf32.f32 "
        "{%0,%1,%2,%3},{%4,%5,%6,%7},{%8,%9},{%0,%1,%2,%3};"
        : "+f"(d[0]), "+f"(d[1]), "+f"(d[2]), "+f"(d[3])
        : "r"(a[0]), "r"(a[1]), "r"(a[2]), "r"(a[3]), "r"(b[0]), "r"(b[1]));
}
__device__ __forceinline__ void mma_bf16(float d[4], const unsigned a[4], const unsigned b[2]) {
    asm volatile(
        "mma.sync.aligned.m16n8k16.row.col.f32.bf16.bf16.f32 "
        "{%0,%1,%2,%3},{%4,%5,%6,%7},{%8,%9},{%0,%1,%2,%3};"
        : "+f"(d[0]), "+f"(d[1]), "+f"(d[2]), "+f"(d[3])
        : "r"(a[0]), "r"(a[1]), "r"(a[2]), "r"(a[3]), "r"(b[0]), "r"(b[1]));
}

__device__ __forceinline__ void cp_async16(uint32_t smem_addr, const void* gptr) {
    asm volatile("cp.async.cg.shared.global [%0], [%1], 16;\n"
                 :: "r"(smem_addr), "l"(gptr));
}
__device__ __forceinline__ void cp_commit() {
    asm volatile("cp.async.commit_group;\n" ::: "memory");
}
template <int N>
__device__ __forceinline__ void cp_wait() {
    asm volatile("cp.async.wait_group %0;\n" :: "n"(N) : "memory");
}

// ---------------------------------------------------------------------------
// LayerNorm: one block per row, 256 threads, D=1024. Output rounded to tf32.
// ---------------------------------------------------------------------------
__global__ __launch_bounds__(256) void ln_kernel(const float* __restrict__ x,
                                                 const float* __restrict__ gamma,
                                                 const float* __restrict__ beta,
                                                 float* __restrict__ y) {
    const int row = blockIdx.x;
    const int tid = threadIdx.x;
    const float4 v = reinterpret_cast<const float4*>(x + (size_t)row * cfg::DC)[tid];
    float s  = v.x + v.y + v.z + v.w;
    float sq = v.x * v.x + v.y * v.y + v.z * v.z + v.w * v.w;
#pragma unroll
    for (int o = 16; o; o >>= 1) {
        s  += __shfl_xor_sync(0xffffffffu, s, o);
        sq += __shfl_xor_sync(0xffffffffu, sq, o);
    }
    __shared__ float ssum[8], ssq[8];
    if ((tid & 31) == 0) { ssum[tid >> 5] = s; ssq[tid >> 5] = sq; }
    __syncthreads();
    float ts = 0.f, tq = 0.f;
#pragma unroll
    for (int i = 0; i < 8; i++) { ts += ssum[i]; tq += ssq[i]; }
    const float mu  = ts * (1.f / cfg::DC);
    const float var = tq * (1.f / cfg::DC) - mu * mu;
    const float rs  = rsqrtf(var + 1e-5f);
    const float4 g4 = reinterpret_cast<const float4*>(gamma)[tid];
    const float4 b4 = reinterpret_cast<const float4*>(beta)[tid];
    float4 o;
    o.x = to_tf32((v.x - mu) * rs * g4.x + b4.x);
    o.y = to_tf32((v.y - mu) * rs * g4.y + b4.y);
    o.z = to_tf32((v.z - mu) * rs * g4.z + b4.z);
    o.w = to_tf32((v.w - mu) * rs * g4.w + b4.w);
    reinterpret_cast<float4*>(y + (size_t)row * cfg::DC)[tid] = o;
}

// ---------------------------------------------------------------------------
// Weight transpose: W[K][N] -> Wt[N][K], rounded to tf32.
// ---------------------------------------------------------------------------
__global__ __launch_bounds__(256) void transpose_kernel(const float* __restrict__ W,
                                                        float* __restrict__ Wt,
                                                        int K, int N) {
    __shared__ float t[32][33];
    const int k0 = blockIdx.y * 32, n0 = blockIdx.x * 32;
    const int tx = threadIdx.x & 31, ty = threadIdx.x >> 5;  // 32 x 8
#pragma unroll
    for (int j = 0; j < 4; j++)
        t[ty + j * 8][tx] = W[(size_t)(k0 + ty + j * 8) * N + n0 + tx];
    __syncthreads();
#pragma unroll
    for (int j = 0; j < 4; j++)
        Wt[(size_t)(n0 + ty + j * 8) * K + k0 + tx] = to_tf32(t[tx][ty + j * 8]);
}

// ---------------------------------------------------------------------------
// tf32 GEMM v3: C[M,N] = act(A[M,K] @ Wt[N,K]^T + bias) (+ res)
// BM=128 BN=128 BK=32, 256 threads (8 warps 2x4), warp tile 64x32.
// cp.async 3-stage pipeline, ONE __syncthreads per k-iter, forced 2 CTA/SM.
// ---------------------------------------------------------------------------
__device__ __forceinline__ float gelu_exact(float x) {
    return 0.5f * x * (1.f + erff(x * 0.70710678118654752f));
}

constexpr int STAGES = 3;

#define EL(v, i) (((const float*)&(v))[i])

template <bool GELU, bool RES>
__global__ __launch_bounds__(256, 2) void gemm2_kernel(const float* __restrict__ A,
                                                       const float* __restrict__ Wt,
                                                       const float* __restrict__ bias,
                                                       float* __restrict__ C,
                                                       const float* __restrict__ res,
                                                       int M, int N, int K) {
    extern __shared__ float sm[];
    float* As = sm;                        // [STAGES][128*32]
    float* Bs = sm + STAGES * 128 * 32;    // [STAGES][128*32]  (n-major)

    const int tid  = threadIdx.x;
    const int lane = tid & 31;
    const int warp = tid >> 5;
    const int g = lane >> 2, c = lane & 3;
    const int wm = (warp >> 2) * 64;   // 0,64
    const int wn = (warp & 3) * 32;    // 0..96
    const int bm = blockIdx.y * 128;
    const int bn = blockIdx.x * 128;

    // cp.async assignment: 2 threads per row, 4 chunks (16B) each
    const int lrow = tid >> 1;           // 0..127
    const int lch0 = (tid & 1) * 4;      // 0 or 4
    const float* Ag = A  + (size_t)(bm + lrow) * K + lch0 * 4;
    const float* Bg = Wt + (size_t)(bn + lrow) * K + lch0 * 4;

    const uint32_t a_smem = smem_u32(As) + (uint32_t)(lrow * 128);
    const uint32_t b_smem = smem_u32(Bs) + (uint32_t)(lrow * 128);
    uint32_t dstoff[4];
#pragma unroll
    for (int j = 0; j < 4; j++) dstoff[j] = (uint32_t)(((lch0 + j) ^ (lrow & 7)) * 16);

    float acc[4][4][4];
#pragma unroll
    for (int mt = 0; mt < 4; mt++)
#pragma unroll
        for (int nt = 0; nt < 4; nt++)
#pragma unroll
            for (int i = 0; i < 4; i++) acc[mt][nt][i] = 0.f;

    const int KT = K >> 5;

    // prologue: fill stages 0 and 1 as separate groups
#pragma unroll
    for (int s = 0; s < STAGES - 1; s++) {
        const float* ag = Ag + s * 32;
        const float* bg = Bg + s * 32;
#pragma unroll
        for (int j = 0; j < 4; j++)
            cp_async16(a_smem + s * 16384 + dstoff[j], ag + j * 4);
#pragma unroll
        for (int j = 0; j < 4; j++)
            cp_async16(b_smem + s * 16384 + dstoff[j], bg + j * 4);
        cp_commit();
    }

    const int ch0 = ((2 * c) ^ g) * 4;       // phys float offset of logical chunk 2c
    const int ch1 = ((2 * c + 1) ^ g) * 4;

    for (int kt = 0; kt < KT; kt++) {
        cp_wait<STAGES - 2>();   // stage kt's group retired
        __syncthreads();         // all warps done reading stage (kt-1)%3

        // prefetch stage kt+2 (overwrites buffer read at iter kt-1 — safe)
        const int ktn = kt + STAGES - 1;
        if (ktn < KT) {
            const int s = ktn % STAGES;
            const float* ag = Ag + ktn * 32;
            const float* bg = Bg + ktn * 32;
#pragma unroll
            for (int j = 0; j < 4; j++)
                cp_async16(a_smem + s * 16384 + dstoff[j], ag + j * 4);
#pragma unroll
            for (int j = 0; j < 4; j++)
                cp_async16(b_smem + s * 16384 + dstoff[j], bg + j * 4);
        }
        cp_commit();

        const float* Ab = As + (kt % STAGES) * 4096;
        const float* Bb = Bs + (kt % STAGES) * 4096;

        float4 bf0[4], bf1[4];
#pragma unroll
        for (int nt = 0; nt < 4; nt++) {
            const float* bp = Bb + (wn + nt * 8 + g) * 32;
            bf0[nt] = *(const float4*)(bp + ch0);
            bf1[nt] = *(const float4*)(bp + ch1);
        }
#pragma unroll
        for (int mt = 0; mt < 4; mt++) {
            const float* ap  = Ab + (wm + mt * 16 + g) * 32;
            const float* ap2 = ap + 8 * 32;
            const float4 a00 = *(const float4*)(ap + ch0);
            const float4 a01 = *(const float4*)(ap + ch1);
            const float4 a10 = *(const float4*)(ap2 + ch0);
            const float4 a11 = *(const float4*)(ap2 + ch1);
#pragma unroll
            for (int m = 0; m < 4; m++) {
                const int e = 2 * (m & 1);
                const float4& al = (m < 2) ? a00 : a01;
                const float4& ah = (m < 2) ? a10 : a11;
                unsigned afr[4] = { fu(EL(al, e)), fu(EL(ah, e)),
                                    fu(EL(al, e + 1)), fu(EL(ah, e + 1)) };
#pragma unroll
                for (int nt = 0; nt < 4; nt++) {
                    const float4& bl = (m < 2) ? bf0[nt] : bf1[nt];
                    unsigned bfr[2] = { fu(EL(bl, e)), fu(EL(bl, e + 1)) };
                    mma_tf32(acc[mt][nt], afr, bfr);
                }
            }
        }
    }

    // epilogue
#pragma unroll
    for (int nt = 0; nt < 4; nt++) {
        const int col = bn + wn + nt * 8 + 2 * c;
        const float b0v = bias[col], b1v = bias[col + 1];
#pragma unroll
        for (int mt = 0; mt < 4; mt++) {
            const int r0 = bm + wm + mt * 16 + g;
            float x0 = acc[mt][nt][0] + b0v;
            float x1 = acc[mt][nt][1] + b1v;
            float x2 = acc[mt][nt][2] + b0v;
            float x3 = acc[mt][nt][3] + b1v;
            if (GELU) {
                x0 = to_tf32(gelu_exact(x0)); x1 = to_tf32(gelu_exact(x1));
                x2 = to_tf32(gelu_exact(x2)); x3 = to_tf32(gelu_exact(x3));
            }
            if (RES) {
                const float2 r0v = *(const float2*)(res + (size_t)r0 * N + col);
                const float2 r1v = *(const float2*)(res + (size_t)(r0 + 8) * N + col);
                x0 += r0v.x; x1 += r0v.y; x2 += r1v.x; x3 += r1v.y;
            }
            *(float2*)(C + (size_t)r0 * N + col)       = make_float2(x0, x1);
            *(float2*)(C + (size_t)(r0 + 8) * N + col) = make_float2(x2, x3);
        }
    }
}

// ---------------------------------------------------------------------------
// Flash attention: grid (NQ/128, H, B), 256 threads (8 warps x 16 query rows)
// ---------------------------------------------------------------------------
__global__ __launch_bounds__(256, 2) void attn_kernel(const float* __restrict__ Q,
                                                      const float* __restrict__ Kb,
                                                      const float* __restrict__ Vb,
                                                      const float* __restrict__ nk,
                                                      const float* __restrict__ X,
                                                      float* __restrict__ Hres) {
    extern __shared__ char smraw[];
    float* Qs = (float*)smraw;               // 128*64 fp32 (swizzled)
    float* Ks = Qs + 128 * 64;               // 64*64 fp32 (swizzled)
    unsigned* VsT = (unsigned*)(Ks + 64 * 64);  // [dh][keypair] bf16x2, 64*32 u32

    const int b = blockIdx.z, h = blockIdx.y;
    const int q0 = blockIdx.x * 128;
    const int tid = threadIdx.x, lane = tid & 31, warp = tid >> 5;
    const int g = lane >> 2, c = lane & 3;
    const int R0 = warp * 16;
    const int qrowbase = b * cfg::NQC + q0;
    const int hc = h * cfg::DHC;

    {
        const int r = tid >> 4;
        const int col = (tid & 15) << 2;
#pragma unroll
        for (int i = 0; i < 8; i++) {
            const int rr = r + i * 16;
            float4 v = *(const float4*)(Q + (size_t)(qrowbase + rr) * cfg::DC + hc + col);
            const int sc = col ^ ((rr & 7) << 2);
            *(float4*)(Qs + rr * 64 + sc) =
                make_float4(to_tf32(v.x), to_tf32(v.y), to_tf32(v.z), to_tf32(v.w));
        }
    }

    float m_lo = -1e30f, m_hi = -1e30f;
    float l_lo = 0.f, l_hi = 0.f;
    float o[8][4];
#pragma unroll
    for (int nt = 0; nt < 8; nt++)
#pragma unroll
        for (int i = 0; i < 4; i++) o[nt][i] = 0.f;

    const float scale = 0.03125f;  // 1/sqrt(1024)
    const int NTILES = 33;         // ceil(2049/64)

    for (int kt = 0; kt < NTILES; kt++) {
        const int kb = kt * 64;
        __syncthreads();
        {
            const int r = tid >> 4;
            const int col = (tid & 15) << 2;
#pragma unroll
            for (int i = 0; i < 4; i++) {
                const int rr = r + i * 16;
                const int key = kb + rr;
                float4 kv, vv;
                if (key < cfg::NKVC) {
                    kv = *(const float4*)(Kb + (size_t)(b * cfg::NKVC + key) * cfg::DC + hc + col);
                    vv = *(const float4*)(Vb + (size_t)(b * cfg::NKVC + key) * cfg::DC + hc + col);
                } else if (key == cfg::NKVC) {
                    kv = *(const float4*)(nk + hc + col);
                    vv = make_float4(0.f, 0.f, 0.f, 0.f);
                } else {
                    kv = make_float4(0.f, 0.f, 0.f, 0.f);
                    vv = make_float4(0.f, 0.f, 0.f, 0.f);
                }
                const int sc = col ^ ((rr & 7) << 2);
                *(float4*)(Ks + rr * 64 + sc) =
                    make_float4(to_tf32(kv.x), to_tf32(kv.y), to_tf32(kv.z), to_tf32(kv.w));
                const float* vp = &vv.x;
#pragma unroll
                for (int j = 0; j < 4; j++) {
                    const int dh = col + j;
                    const int kp = rr >> 1;
                    const int idx = dh * 32 + (kp ^ ((dh & 7) << 2));
                    __nv_bfloat16* p = ((__nv_bfloat16*)&VsT[idx]) + (rr & 1);
                    *p = __float2bfloat16(vp[j]);
                }
            }
        }
        __syncthreads();

        float s[8][4];
#pragma unroll
        for (int nt = 0; nt < 8; nt++)
#pragma unroll
            for (int i = 0; i < 4; i++) s[nt][i] = 0.f;
#pragma unroll
        for (int kk = 0; kk < 8; kk++) {
            const int K0 = kk * 8;
            const int cs0 = (K0 + c) ^ (g << 2);
            const int cs1 = (K0 + c + 4) ^ (g << 2);
            unsigned a[4];
            a[0] = fu(Qs[(R0 + g) * 64 + cs0]);
            a[1] = fu(Qs[(R0 + 8 + g) * 64 + cs0]);
            a[2] = fu(Qs[(R0 + g) * 64 + cs1]);
            a[3] = fu(Qs[(R0 + 8 + g) * 64 + cs1]);
#pragma unroll
            for (int nt = 0; nt < 8; nt++) {
                const int key = nt * 8 + g;
                unsigned bb[2];
                bb[0] = fu(Ks[key * 64 + cs0]);
                bb[1] = fu(Ks[key * 64 + cs1]);
                mma_tf32(s[nt], a, bb);
            }
        }
#pragma unroll
        for (int nt = 0; nt < 8; nt++)
#pragma unroll
            for (int i = 0; i < 4; i++) s[nt][i] *= scale;
        if (kb + 64 > cfg::NKVC + 1) {
#pragma unroll
            for (int nt = 0; nt < 8; nt++) {
                const int col0 = kb + nt * 8 + 2 * c;
                if (col0 > cfg::NKVC)     { s[nt][0] = -1e30f; s[nt][2] = -1e30f; }
                if (col0 + 1 > cfg::NKVC) { s[nt][1] = -1e30f; s[nt][3] = -1e30f; }
            }
        }
        float rmax_lo = -1e30f, rmax_hi = -1e30f;
#pragma unroll
        for (int nt = 0; nt < 8; nt++) {
            rmax_lo = fmaxf(rmax_lo, fmaxf(s[nt][0], s[nt][1]));
            rmax_hi = fmaxf(rmax_hi, fmaxf(s[nt][2], s[nt][3]));
        }
        rmax_lo = fmaxf(rmax_lo, __shfl_xor_sync(0xffffffffu, rmax_lo, 1));
        rmax_lo = fmaxf(rmax_lo, __shfl_xor_sync(0xffffffffu, rmax_lo, 2));
        rmax_hi = fmaxf(rmax_hi, __shfl_xor_sync(0xffffffffu, rmax_hi, 1));
        rmax_hi = fmaxf(rmax_hi, __shfl_xor_sync(0xffffffffu, rmax_hi, 2));
        const float mn_lo = fmaxf(m_lo, rmax_lo);
        const float mn_hi = fmaxf(m_hi, rmax_hi);
        const float alpha_lo = __expf(m_lo - mn_lo);
        const float alpha_hi = __expf(m_hi - mn_hi);
        m_lo = mn_lo; m_hi = mn_hi;

        float rs_lo = 0.f, rs_hi = 0.f;
        unsigned pfrag[4][4];
#pragma unroll
        for (int t = 0; t < 4; t++) {
            const float p00 = __expf(s[2 * t][0] - m_lo);
            const float p01 = __expf(s[2 * t][1] - m_lo);
            const float p10 = __expf(s[2 * t][2] - m_hi);
            const float p11 = __expf(s[2 * t][3] - m_hi);
            const float p20 = __expf(s[2 * t + 1][0] - m_lo);
            const float p21 = __expf(s[2 * t + 1][1] - m_lo);
            const float p30 = __expf(s[2 * t + 1][2] - m_hi);
            const float p31 = __expf(s[2 * t + 1][3] - m_hi);
            rs_lo += p00 + p01 + p20 + p21;
            rs_hi += p10 + p11 + p30 + p31;
            __nv_bfloat162 t0 = __floats2bfloat162_rn(p00, p01);
            __nv_bfloat162 t1 = __floats2bfloat162_rn(p10, p11);
            __nv_bfloat162 t2 = __floats2bfloat162_rn(p20, p21);
            __nv_bfloat162 t3 = __floats2bfloat162_rn(p30, p31);
            pfrag[t][0] = *(unsigned*)&t0;
            pfrag[t][1] = *(unsigned*)&t1;
            pfrag[t][2] = *(unsigned*)&t2;
            pfrag[t][3] = *(unsigned*)&t3;
        }
        rs_lo += __shfl_xor_sync(0xffffffffu, rs_lo, 1);
        rs_lo += __shfl_xor_sync(0xffffffffu, rs_lo, 2);
        rs_hi += __shfl_xor_sync(0xffffffffu, rs_hi, 1);
        rs_hi += __shfl_xor_sync(0xffffffffu, rs_hi, 2);
        l_lo = l_lo * alpha_lo + rs_lo;
        l_hi = l_hi * alpha_hi + rs_hi;
#pragma unroll
        for (int nt = 0; nt < 8; nt++) {
            o[nt][0] *= alpha_lo; o[nt][1] *= alpha_lo;
            o[nt][2] *= alpha_hi; o[nt][3] *= alpha_hi;
        }
#pragma unroll
        for (int t = 0; t < 4; t++) {
#pragma unroll
            for (int nt = 0; nt < 8; nt++) {
                const int dh = nt * 8 + g;
                unsigned bb[2];
                bb[0] = VsT[dh * 32 + ((8 * t + c) ^ ((dh & 7) << 2))];
                bb[1] = VsT[dh * 32 + ((8 * t + c + 4) ^ ((dh & 7) << 2))];
                mma_bf16(o[nt], pfrag[t], bb);
            }
        }
    }

    const float il_lo = 1.f / l_lo;
    const float il_hi = 1.f / l_hi;
    const int row  = qrowbase + R0 + g;
    const int row2 = row + 8;
#pragma unroll
    for (int nt = 0; nt < 8; nt++) {
        const int col = hc + nt * 8 + 2 * c;
        const float2 x0 = *(const float2*)(X + (size_t)row * cfg::DC + col);
        const float2 x1 = *(const float2*)(X + (size_t)row2 * cfg::DC + col);
        *(float2*)(Hres + (size_t)row * cfg::DC + col) =
            make_float2(o[nt][0] * il_lo + x0.x, o[nt][1] * il_lo + x0.y);
        *(float2*)(Hres + (size_t)row2 * cfg::DC + col) =
            make_float2(o[nt][2] * il_hi + x1.x, o[nt][3] * il_hi + x1.y);
    }
}

// ---------------------------------------------------------------------------
extern "C" void kernel_launch(void* const* d_in, const int* in_sizes, int n_in,
                              void* d_out, int out_size) {
    const float* X     = (const float*)d_in[0];
    const float* Y     = (const float*)d_in[1];
    const float* Wq    = (const float*)d_in[2];
    const float* bq    = (const float*)d_in[3];
    const float* Wk    = (const float*)d_in[4];
    const float* bk    = (const float*)d_in[5];
    const float* Wv    = (const float*)d_in[6];
    const float* bv    = (const float*)d_in[7];
    const float* nullk = (const float*)d_in[8];
    const float* g0    = (const float*)d_in[9];
    const float* b0    = (const float*)d_in[10];
    const float* g0kv  = (const float*)d_in[11];
    const float* b0kv  = (const float*)d_in[12];
    const float* g1    = (const float*)d_in[13];
    const float* b1    = (const float*)d_in[14];
    const float* W1    = (const float*)d_in[15];
    const float* bf1   = (const float*)d_in[16];
    const float* W2    = (const float*)d_in[17];
    const float* bf2   = (const float*)d_in[18];
    float* out = (float*)d_out;

    float *Xn, *Yn, *Qp, *Kp, *Vp, *Hres, *Hr, *Hid;
    float *Wqt, *Wkt, *Wvt, *W1t, *W2t;
    cudaGetSymbolAddress((void**)&Xn,   g_Xn);
    cudaGetSymbolAddress((void**)&Yn,   g_Yn);
    cudaGetSymbolAddress((void**)&Qp,   g_Qp);
    cudaGetSymbolAddress((void**)&Kp,   g_Kp);
    cudaGetSymbolAddress((void**)&Vp,   g_Vp);
    cudaGetSymbolAddress((void**)&Hres, g_Hres);
    cudaGetSymbolAddress((void**)&Hr,   g_Hr);
    cudaGetSymbolAddress((void**)&Hid,  g_Hid);
    cudaGetSymbolAddress((void**)&Wqt,  g_Wqt);
    cudaGetSymbolAddress((void**)&Wkt,  g_Wkt);
    cudaGetSymbolAddress((void**)&Wvt,  g_Wvt);
    cudaGetSymbolAddress((void**)&W1t,  g_W1t);
    cudaGetSymbolAddress((void**)&W2t,  g_W2t);

    const int gemm_smem = STAGES * (128 * 32 + 128 * 32) * (int)sizeof(float);  // 98304
    const int attn_smem = (128 * 64 + 64 * 64) * (int)sizeof(float) + 64 * 32 * 4;  // 57344
    cudaFuncSetAttribute(gemm2_kernel<false, false>,
                         cudaFuncAttributeMaxDynamicSharedMemorySize, gemm_smem);
    cudaFuncSetAttribute(gemm2_kernel<true, false>,
                         cudaFuncAttributeMaxDynamicSharedMemorySize, gemm_smem);
    cudaFuncSetAttribute(gemm2_kernel<false, true>,
                         cudaFuncAttributeMaxDynamicSharedMemorySize, gemm_smem);
    cudaFuncSetAttribute(attn_kernel,
                         cudaFuncAttributeMaxDynamicSharedMemorySize, attn_smem);

    // weight transposes (+ tf32 rounding)
    transpose_kernel<<<dim3(cfg::DC / 32, cfg::DC / 32), 256>>>(Wq, Wqt, cfg::DC, cfg::DC);
    transpose_kernel<<<dim3(cfg::DC / 32, cfg::DC / 32), 256>>>(Wk, Wkt, cfg::DC, cfg::DC);
    transpose_kernel<<<dim3(cfg::DC / 32, cfg::DC / 32), 256>>>(Wv, Wvt, cfg::DC, cfg::DC);
    transpose_kernel<<<dim3(cfg::DFF / 32, cfg::DC / 32), 256>>>(W1, W1t, cfg::DC, cfg::DFF);
    transpose_kernel<<<dim3(cfg::DC / 32, cfg::DFF / 32), 256>>>(W2, W2t, cfg::DFF, cfg::DC);

    ln_kernel<<<cfg::MR, 256>>>(X, g0, b0, Xn);
    ln_kernel<<<cfg::MR, 256>>>(Y, g0kv, b0kv, Yn);

    gemm2_kernel<false, false><<<dim3(cfg::DC / 128, cfg::MR / 128), 256, gemm_smem>>>(
        Xn, Wqt, bq, Qp, nullptr, cfg::MR, cfg::DC, cfg::DC);
    gemm2_kernel<false, false><<<dim3(cfg::DC / 128, cfg::MR / 128), 256, gemm_smem>>>(
        Yn, Wkt, bk, Kp, nullptr, cfg::MR, cfg::DC, cfg::DC);
    gemm2_kernel<false, false><<<dim3(cfg::DC / 128, cfg::MR / 128), 256, gemm_smem>>>(
        Yn, Wvt, bv, Vp, nullptr, cfg::MR, cfg::DC, cfg::DC);

    attn_kernel<<<dim3(cfg::NQC / 128, 16, cfg::BB), 256, attn_smem>>>(
        Qp, Kp, Vp, nullk, X, Hres);

    ln_kernel<<<cfg::MR, 256>>>(Hres, g1, b1, Hr);

    gemm2_kernel<true, false><<<dim3(cfg::DFF / 128, cfg::MR / 128), 256, gemm_smem>>>(
        Hr, W1t, bf1, Hid, nullptr, cfg::MR, cfg::DFF, cfg::DC);
    gemm2_kernel<false, true><<<dim3(cfg::DC / 128, cfg::MR / 128), 256, gemm_smem>>>(
        Hid, W2t, bf2, out, Hres, cfg::MR, cfg::DC, cfg::DFF);
}

// round 6
// speedup vs baseline: 1.6326x; 1.5319x over previous
#include <cuda_runtime.h>
#include <cuda_fp16.h>
#include <cuda_bf16.h>
#include <cstdint>
#include <math.h>

// ---------------------------------------------------------------------------
// MAB block: B=2, NQ=NKV=2048, D=1024, H=16, DH=64
// fp16 mma.sync m16n8k16 GEMMs (k-pair-permuted operands, cp.async 3-stage) +
// flash attention (tf32 QK^T, bf16 PV)
// ---------------------------------------------------------------------------

namespace cfg {
constexpr int BB   = 2;
constexpr int NQC  = 2048;
constexpr int NKVC = 2048;
constexpr int DC   = 1024;
constexpr int DHC  = 64;
constexpr int MR   = BB * NQC;   // 4096 rows
constexpr int DFF  = 4 * DC;     // 4096
}

// scratch (device globals; allocation APIs are forbidden)
__device__ __half g_Xn16[cfg::MR * cfg::DC];
__device__ __half g_Yn16[cfg::MR * cfg::DC];
__device__ __half g_Hr16[cfg::MR * cfg::DC];
__device__ __half g_Hid16[cfg::MR * cfg::DFF];
__device__ float  g_Qp[cfg::MR * cfg::DC];
__device__ float  g_KVp[cfg::MR * 2 * cfg::DC];   // fused K|V, row stride 2048
__device__ float  g_Hres[cfg::MR * cfg::DC];
// transposed fp16 (k-pair-permuted) weights
__device__ __half g_Wqt16[cfg::DC * cfg::DC];
__device__ __half g_Wkvt16[2 * cfg::DC * cfg::DC];
__device__ __half g_W1t16[cfg::DC * cfg::DFF];
__device__ __half g_W2t16[cfg::DFF * cfg::DC];

// ---------------------------------------------------------------------------
// helpers
// ---------------------------------------------------------------------------
__device__ __forceinline__ float to_tf32(float x) {
    asm volatile("cvt.rna.tf32.f32 %0, %0;" : "+f"(x));
    return x;
}
__device__ __forceinline__ unsigned fu(float x) { return __float_as_uint(x); }

// pair permutation within a 16-pair (32-element) k-group
__device__ __host__ __forceinline__ int permp(int p) { return ((p & 3) << 2) | (p >> 2); }

__device__ __forceinline__ uint32_t smem_u32(const void* p) {
    uint32_t a;
    asm("{ .reg .u64 t; cvta.to.shared.u64 t, %1; cvt.u32.u64 %0, t; }"
        : "=r"(a) : "l"(p));
    return a;
}

__device__ __forceinline__ void cp_async16(uint32_t smem_addr, const void* gptr) {
    asm volatile("cp.async.cg.shared.global [%0], [%1], 16;\n"
                 :: "r"(smem_addr), "l"(gptr));
}
__device__ __forceinline__ void cp_commit() {
    asm volatile("cp.async.commit_group;\n" ::: "memory");
}
template <int N>
__device__ __forceinline__ void cp_wait() {
    asm volatile("cp.async.wait_group %0;\n" :: "n"(N) : "memory");
}

__device__ __forceinline__ void mma_f16(float d[4], unsigned a0, unsigned a1,
                                        unsigned a2, unsigned a3,
                                        unsigned b0, unsigned b1) {
    asm volatile(
        "mma.sync.aligned.m16n8k16.row.col.f32.f16.f16.f32 "
        "{%0,%1,%2,%3},{%4,%5,%6,%7},{%8,%9},{%0,%1,%2,%3};"
        : "+f"(d[0]), "+f"(d[1]), "+f"(d[2]), "+f"(d[3])
        : "r"(a0), "r"(a1), "r"(a2), "r"(a3), "r"(b0), "r"(b1));
}
__device__ __forceinline__ void mma_tf32(float d[4], const unsigned a[4], const unsigned b[2]) {
    asm volatile(
        "mma.sync.aligned.m16n8k8.row.col.f32.tf32.tf32.f32 "
        "{%0,%1,%2,%3},{%4,%5,%6,%7},{%8,%9},{%0,%1,%2,%3};"
        : "+f"(d[0]), "+f"(d[1]), "+f"(d[2]), "+f"(d[3])
        : "r"(a[0]), "r"(a[1]), "r"(a[2]), "r"(a[3]), "r"(b[0]), "r"(b[1]));
}
__device__ __forceinline__ void mma_bf16(float d[4], const unsigned a[4], const unsigned b[2]) {
    asm volatile(
        "mma.sync.aligned.m16n8k16.row.col.f32.bf16.bf16.f32 "
        "{%0,%1,%2,%3},{%4,%5,%6,%7},{%8,%9},{%0,%1,%2,%3};"
        : "+f"(d[0]), "+f"(d[1]), "+f"(d[2]), "+f"(d[3])
        : "r"(a[0]), "r"(a[1]), "r"(a[2]), "r"(a[3]), "r"(b[0]), "r"(b[1]));
}

// ---------------------------------------------------------------------------
// LayerNorm: one block/row, 256 threads, D=1024. Output fp16 k-pair-permuted.
// ---------------------------------------------------------------------------
__global__ __launch_bounds__(256) void ln_kernel(const float* __restrict__ x,
                                                 const float* __restrict__ gamma,
                                                 const float* __restrict__ beta,
                                                 __half2* __restrict__ y) {
    const int row = blockIdx.x;
    const int tid = threadIdx.x;
    const float4 v = reinterpret_cast<const float4*>(x + (size_t)row * cfg::DC)[tid];
    float s  = v.x + v.y + v.z + v.w;
    float sq = v.x * v.x + v.y * v.y + v.z * v.z + v.w * v.w;
#pragma unroll
    for (int o = 16; o; o >>= 1) {
        s  += __shfl_xor_sync(0xffffffffu, s, o);
        sq += __shfl_xor_sync(0xffffffffu, sq, o);
    }
    __shared__ float ssum[8], ssq[8];
    if ((tid & 31) == 0) { ssum[tid >> 5] = s; ssq[tid >> 5] = sq; }
    __syncthreads();
    float ts = 0.f, tq = 0.f;
#pragma unroll
    for (int i = 0; i < 8; i++) { ts += ssum[i]; tq += ssq[i]; }
    const float mu  = ts * (1.f / cfg::DC);
    const float var = tq * (1.f / cfg::DC) - mu * mu;
    const float rs  = rsqrtf(var + 1e-5f);
    const float4 g4 = reinterpret_cast<const float4*>(gamma)[tid];
    const float4 b4 = reinterpret_cast<const float4*>(beta)[tid];
    float4 o;
    o.x = (v.x - mu) * rs * g4.x + b4.x;
    o.y = (v.y - mu) * rs * g4.y + b4.y;
    o.z = (v.z - mu) * rs * g4.z + b4.z;
    o.w = (v.w - mu) * rs * g4.w + b4.w;
    const int kp = 2 * tid;               // global pair index (even)
    const int t  = kp >> 4;               // 16-pair group
    const int p0 = kp & 15;
    __half2* yr = y + (size_t)row * (cfg::DC / 2) + (t << 4);
    yr[permp(p0)]     = __floats2half2_rn(o.x, o.y);
    yr[permp(p0 + 1)] = __floats2half2_rn(o.z, o.w);
}

// ---------------------------------------------------------------------------
// Weight transpose: W[K][N] -> Wt16[N][K] fp16, k-pair-permuted.
// ---------------------------------------------------------------------------
__global__ __launch_bounds__(256) void transpose16_kernel(const float* __restrict__ W,
                                                          __half2* __restrict__ Wt,
                                                          int K, int N) {
    __shared__ float t[32][33];
    const int k0 = blockIdx.y * 32, n0 = blockIdx.x * 32;
    const int tx = threadIdx.x & 31, ty = threadIdx.x >> 5;
#pragma unroll
    for (int j = 0; j < 4; j++)
        t[ty + j * 8][tx] = W[(size_t)(k0 + ty + j * 8) * N + n0 + tx];
    __syncthreads();
    const int nl = threadIdx.x >> 3;       // 0..31 local n
    const int pb = threadIdx.x & 7;        // pair base
    __half2* outr = Wt + (((size_t)(n0 + nl) * K + k0) >> 1);
#pragma unroll
    for (int q = 0; q < 2; q++) {
        const int p = pb + q * 8;          // 0..15
        outr[permp(p)] = __floats2half2_rn(t[2 * p][nl], t[2 * p + 1][nl]);
    }
}

// ---------------------------------------------------------------------------
// fp16 GEMM: C[M,N] = act(A[M,K] @ Wt[N,K]^T + bias) (+ res)
// A, Wt: fp16 k-pair-permuted. BM=BN=128, BK=32 (64B rows), 256 threads,
// warp tile 64x32, 3-stage cp.async, single sync/iter, 2 CTA/SM.
// GELU16: gelu + fp16-permuted output (for FFN1); else fp32 output.
// ---------------------------------------------------------------------------
__device__ __forceinline__ float gelu_exact(float x) {
    return 0.5f * x * (1.f + erff(x * 0.70710678118654752f));
}

constexpr int GSTAGE = 128 * 64 * 2 * 2;   // A+B stage bytes = 32768? no:
// A: 128 rows * 64B = 8192; B: same = 8192; stage = 16384.
constexpr int STAGE_BYTES = 16384;

template <bool GELU16, bool RES>
__global__ __launch_bounds__(256, 2) void gemm_h(const __half* __restrict__ A,
                                                 const __half* __restrict__ Wt,
                                                 const float* __restrict__ bias1,
                                                 const float* __restrict__ bias2,
                                                 int split,
                                                 void* __restrict__ Cout,
                                                 const float* __restrict__ res,
                                                 int M, int N, int K) {
    extern __shared__ char smc[];

    const int tid  = threadIdx.x;
    const int lane = tid & 31;
    const int warp = tid >> 5;
    const int g = lane >> 2, c = lane & 3;
    const int wm = (warp >> 2) * 64;
    const int wn = (warp & 3) * 32;
    const int bm = blockIdx.y * 128;
    const int bn = blockIdx.x * 128;

    // loader: each thread: 2 A chunks + 2 B chunks (16B each)
    const int arow = tid >> 1;
    const int ach  = (tid & 1) * 2;
    const __half* Ag = A  + (size_t)(bm + arow) * K + ach * 8;
    const __half* Bg = Wt + (size_t)(bn + arow) * K + ach * 8;
    const uint32_t sa = smem_u32(smc) + (uint32_t)(arow * 64);
    const uint32_t sb = sa + 128 * 64;
    const uint32_t d0 = (uint32_t)(((ach    ) ^ (arow & 3)) * 16);
    const uint32_t d1 = (uint32_t)(((ach + 1) ^ (arow & 3)) * 16);

    float acc[4][4][4];
#pragma unroll
    for (int mt = 0; mt < 4; mt++)
#pragma unroll
        for (int nt = 0; nt < 4; nt++)
#pragma unroll
            for (int i = 0; i < 4; i++) acc[mt][nt][i] = 0.f;

    const int KT = K >> 5;

    auto load_stage = [&](int kt, int s) {
        const uint32_t st = (uint32_t)(s * STAGE_BYTES);
        const __half* ag = Ag + kt * 32;
        const __half* bg = Bg + kt * 32;
        cp_async16(sa + st + d0, ag);
        cp_async16(sa + st + d1, ag + 8);
        cp_async16(sb + st + d0, bg);
        cp_async16(sb + st + d1, bg + 8);
    };

    load_stage(0, 0); cp_commit();
    if (KT > 1) load_stage(1, 1);
    cp_commit();

    const uint32_t choff = (uint32_t)((c ^ (g & 3)) * 16);

    for (int kt = 0; kt < KT; kt++) {
        cp_wait<1>();            // stage kt resident
        __syncthreads();         // everyone done with stage (kt-1)%3

        if (kt + 2 < KT) load_stage(kt + 2, (kt + 2) % 3);
        cp_commit();

        const char* Ab = smc + (kt % 3) * STAGE_BYTES;
        const char* Bb = Ab + 128 * 64;

        uint4 bv[4];
#pragma unroll
        for (int nt = 0; nt < 4; nt++)
            bv[nt] = *(const uint4*)(Bb + (wn + nt * 8 + g) * 64 + choff);
#pragma unroll
        for (int mt = 0; mt < 4; mt++) {
            const char* ap = Ab + (wm + mt * 16 + g) * 64 + choff;
            const uint4 lo = *(const uint4*)ap;
            const uint4 hi = *(const uint4*)(ap + 8 * 64);
#pragma unroll
            for (int nt = 0; nt < 4; nt++) {
                mma_f16(acc[mt][nt], lo.x, hi.x, lo.y, hi.y, bv[nt].x, bv[nt].y);
                mma_f16(acc[mt][nt], lo.z, hi.z, lo.w, hi.w, bv[nt].z, bv[nt].w);
            }
        }
    }

    // epilogue
    if (!GELU16) {
        float* C = (float*)Cout;
#pragma unroll
        for (int nt = 0; nt < 4; nt++) {
            const int col = bn + wn + nt * 8 + 2 * c;
            const float b0v = (col < split) ? bias1[col] : bias2[col - split];
            const float b1v = (col + 1 < split) ? bias1[col + 1] : bias2[col + 1 - split];
#pragma unroll
            for (int mt = 0; mt < 4; mt++) {
                const int r0 = bm + wm + mt * 16 + g;
                float x0 = acc[mt][nt][0] + b0v;
                float x1 = acc[mt][nt][1] + b1v;
                float x2 = acc[mt][nt][2] + b0v;
                float x3 = acc[mt][nt][3] + b1v;
                if (RES) {
                    const float2 r0v = *(const float2*)(res + (size_t)r0 * N + col);
                    const float2 r1v = *(const float2*)(res + (size_t)(r0 + 8) * N + col);
                    x0 += r0v.x; x1 += r0v.y; x2 += r1v.x; x3 += r1v.y;
                }
                *(float2*)(C + (size_t)r0 * N + col)       = make_float2(x0, x1);
                *(float2*)(C + (size_t)(r0 + 8) * N + col) = make_float2(x2, x3);
            }
        }
    } else {
        __half2* C = (__half2*)Cout;
        const int NH = N >> 1;
#pragma unroll
        for (int nt = 0; nt < 4; nt++) {
            const int n = bn + wn + nt * 8 + 2 * c;
            const float b0v = bias1[n], b1v = bias1[n + 1];
            const int h2off = ((n >> 5) << 4) + permp((n >> 1) & 15);
#pragma unroll
            for (int mt = 0; mt < 4; mt++) {
                const int r0 = bm + wm + mt * 16 + g;
                const float x0 = gelu_exact(acc[mt][nt][0] + b0v);
                const float x1 = gelu_exact(acc[mt][nt][1] + b1v);
                const float x2 = gelu_exact(acc[mt][nt][2] + b0v);
                const float x3 = gelu_exact(acc[mt][nt][3] + b1v);
                C[(size_t)r0 * NH + h2off]       = __floats2half2_rn(x0, x1);
                C[(size_t)(r0 + 8) * NH + h2off] = __floats2half2_rn(x2, x3);
            }
        }
    }
}

// ---------------------------------------------------------------------------
// Flash attention: grid (NQ/128, H, B), 256 threads (8 warps x 16 query rows)
// K/V from fused KV buffer (row stride 2048; V at +1024).
// ---------------------------------------------------------------------------
__global__ __launch_bounds__(256, 2) void attn_kernel(const float* __restrict__ Q,
                                                      const float* __restrict__ KV,
                                                      const float* __restrict__ nk,
                                                      const float* __restrict__ X,
                                                      float* __restrict__ Hres) {
    extern __shared__ char smraw[];
    float* Qs = (float*)smraw;
    float* Ks = Qs + 128 * 64;
    unsigned* VsT = (unsigned*)(Ks + 64 * 64);

    const int b = blockIdx.z, h = blockIdx.y;
    const int q0 = blockIdx.x * 128;
    const int tid = threadIdx.x, lane = tid & 31, warp = tid >> 5;
    const int g = lane >> 2, c = lane & 3;
    const int R0 = warp * 16;
    const int qrowbase = b * cfg::NQC + q0;
    const int hc = h * cfg::DHC;

    {
        const int r = tid >> 4;
        const int col = (tid & 15) << 2;
#pragma unroll
        for (int i = 0; i < 8; i++) {
            const int rr = r + i * 16;
            float4 v = *(const float4*)(Q + (size_t)(qrowbase + rr) * cfg::DC + hc + col);
            const int sc = col ^ ((rr & 7) << 2);
            *(float4*)(Qs + rr * 64 + sc) =
                make_float4(to_tf32(v.x), to_tf32(v.y), to_tf32(v.z), to_tf32(v.w));
        }
    }

    float m_lo = -1e30f, m_hi = -1e30f;
    float l_lo = 0.f, l_hi = 0.f;
    float o[8][4];
#pragma unroll
    for (int nt = 0; nt < 8; nt++)
#pragma unroll
        for (int i = 0; i < 4; i++) o[nt][i] = 0.f;

    const float scale = 0.03125f;
    const int NTILES = 33;

    for (int kt = 0; kt < NTILES; kt++) {
        const int kb = kt * 64;
        __syncthreads();
        {
            const int r = tid >> 4;
            const int col = (tid & 15) << 2;
#pragma unroll
            for (int i = 0; i < 4; i++) {
                const int rr = r + i * 16;
                const int key = kb + rr;
                float4 kv, vv;
                if (key < cfg::NKVC) {
                    const float* base = KV + (size_t)(b * cfg::NKVC + key) * 2048 + hc + col;
                    kv = *(const float4*)(base);
                    vv = *(const float4*)(base + cfg::DC);
                } else if (key == cfg::NKVC) {
                    kv = *(const float4*)(nk + hc + col);
                    vv = make_float4(0.f, 0.f, 0.f, 0.f);
                } else {
                    kv = make_float4(0.f, 0.f, 0.f, 0.f);
                    vv = make_float4(0.f, 0.f, 0.f, 0.f);
                }
                const int sc = col ^ ((rr & 7) << 2);
                *(float4*)(Ks + rr * 64 + sc) =
                    make_float4(to_tf32(kv.x), to_tf32(kv.y), to_tf32(kv.z), to_tf32(kv.w));
                const float* vp = &vv.x;
#pragma unroll
                for (int j = 0; j < 4; j++) {
                    const int dh = col + j;
                    const int kp = rr >> 1;
                    const int idx = dh * 32 + (kp ^ ((dh & 7) << 2));
                    __nv_bfloat16* p = ((__nv_bfloat16*)&VsT[idx]) + (rr & 1);
                    *p = __float2bfloat16(vp[j]);
                }
            }
        }
        __syncthreads();

        float s[8][4];
#pragma unroll
        for (int nt = 0; nt < 8; nt++)
#pragma unroll
            for (int i = 0; i < 4; i++) s[nt][i] = 0.f;
#pragma unroll
        for (int kk = 0; kk < 8; kk++) {
            const int K0 = kk * 8;
            const int cs0 = (K0 + c) ^ (g << 2);
            const int cs1 = (K0 + c + 4) ^ (g << 2);
            unsigned a[4];
            a[0] = fu(Qs[(R0 + g) * 64 + cs0]);
            a[1] = fu(Qs[(R0 + 8 + g) * 64 + cs0]);
            a[2] = fu(Qs[(R0 + g) * 64 + cs1]);
            a[3] = fu(Qs[(R0 + 8 + g) * 64 + cs1]);
#pragma unroll
            for (int nt = 0; nt < 8; nt++) {
                const int key = nt * 8 + g;
                unsigned bb[2];
                bb[0] = fu(Ks[key * 64 + cs0]);
                bb[1] = fu(Ks[key * 64 + cs1]);
                mma_tf32(s[nt], a, bb);
            }
        }
#pragma unroll
        for (int nt = 0; nt < 8; nt++)
#pragma unroll
            for (int i = 0; i < 4; i++) s[nt][i] *= scale;
        if (kb + 64 > cfg::NKVC + 1) {
#pragma unroll
            for (int nt = 0; nt < 8; nt++) {
                const int col0 = kb + nt * 8 + 2 * c;
                if (col0 > cfg::NKVC)     { s[nt][0] = -1e30f; s[nt][2] = -1e30f; }
                if (col0 + 1 > cfg::NKVC) { s[nt][1] = -1e30f; s[nt][3] = -1e30f; }
            }
        }
        float rmax_lo = -1e30f, rmax_hi = -1e30f;
#pragma unroll
        for (int nt = 0; nt < 8; nt++) {
            rmax_lo = fmaxf(rmax_lo, fmaxf(s[nt][0], s[nt][1]));
            rmax_hi = fmaxf(rmax_hi, fmaxf(s[nt][2], s[nt][3]));
        }
        rmax_lo = fmaxf(rmax_lo, __shfl_xor_sync(0xffffffffu, rmax_lo, 1));
        rmax_lo = fmaxf(rmax_lo, __shfl_xor_sync(0xffffffffu, rmax_lo, 2));
        rmax_hi = fmaxf(rmax_hi, __shfl_xor_sync(0xffffffffu, rmax_hi, 1));
        rmax_hi = fmaxf(rmax_hi, __shfl_xor_sync(0xffffffffu, rmax_hi, 2));
        const float mn_lo = fmaxf(m_lo, rmax_lo);
        const float mn_hi = fmaxf(m_hi, rmax_hi);
        const float alpha_lo = __expf(m_lo - mn_lo);
        const float alpha_hi = __expf(m_hi - mn_hi);
        m_lo = mn_lo; m_hi = mn_hi;

        float rs_lo = 0.f, rs_hi = 0.f;
        unsigned pfrag[4][4];
#pragma unroll
        for (int t = 0; t < 4; t++) {
            const float p00 = __expf(s[2 * t][0] - m_lo);
            const float p01 = __expf(s[2 * t][1] - m_lo);
            const float p10 = __expf(s[2 * t][2] - m_hi);
            const float p11 = __expf(s[2 * t][3] - m_hi);
            const float p20 = __expf(s[2 * t + 1][0] - m_lo);
            const float p21 = __expf(s[2 * t + 1][1] - m_lo);
            const float p30 = __expf(s[2 * t + 1][2] - m_hi);
            const float p31 = __expf(s[2 * t + 1][3] - m_hi);
            rs_lo += p00 + p01 + p20 + p21;
            rs_hi += p10 + p11 + p30 + p31;
            __nv_bfloat162 t0 = __floats2bfloat162_rn(p00, p01);
            __nv_bfloat162 t1 = __floats2bfloat162_rn(p10, p11);
            __nv_bfloat162 t2 = __floats2bfloat162_rn(p20, p21);
            __nv_bfloat162 t3 = __floats2bfloat162_rn(p30, p31);
            pfrag[t][0] = *(unsigned*)&t0;
            pfrag[t][1] = *(unsigned*)&t1;
            pfrag[t][2] = *(unsigned*)&t2;
            pfrag[t][3] = *(unsigned*)&t3;
        }
        rs_lo += __shfl_xor_sync(0xffffffffu, rs_lo, 1);
        rs_lo += __shfl_xor_sync(0xffffffffu, rs_lo, 2);
        rs_hi += __shfl_xor_sync(0xffffffffu, rs_hi, 1);
        rs_hi += __shfl_xor_sync(0xffffffffu, rs_hi, 2);
        l_lo = l_lo * alpha_lo + rs_lo;
        l_hi = l_hi * alpha_hi + rs_hi;
#pragma unroll
        for (int nt = 0; nt < 8; nt++) {
            o[nt][0] *= alpha_lo; o[nt][1] *= alpha_lo;
            o[nt][2] *= alpha_hi; o[nt][3] *= alpha_hi;
        }
#pragma unroll
        for (int t = 0; t < 4; t++) {
#pragma unroll
            for (int nt = 0; nt < 8; nt++) {
                const int dh = nt * 8 + g;
                unsigned bb[2];
                bb[0] = VsT[dh * 32 + ((8 * t + c) ^ ((dh & 7) << 2))];
                bb[1] = VsT[dh * 32 + ((8 * t + c + 4) ^ ((dh & 7) << 2))];
                mma_bf16(o[nt], pfrag[t], bb);
            }
        }
    }

    const float il_lo = 1.f / l_lo;
    const float il_hi = 1.f / l_hi;
    const int row  = qrowbase + R0 + g;
    const int row2 = row + 8;
#pragma unroll
    for (int nt = 0; nt < 8; nt++) {
        const int col = hc + nt * 8 + 2 * c;
        const float2 x0 = *(const float2*)(X + (size_t)row * cfg::DC + col);
        const float2 x1 = *(const float2*)(X + (size_t)row2 * cfg::DC + col);
        *(float2*)(Hres + (size_t)row * cfg::DC + col) =
            make_float2(o[nt][0] * il_lo + x0.x, o[nt][1] * il_lo + x0.y);
        *(float2*)(Hres + (size_t)row2 * cfg::DC + col) =
            make_float2(o[nt][2] * il_hi + x1.x, o[nt][3] * il_hi + x1.y);
    }
}

// ---------------------------------------------------------------------------
extern "C" void kernel_launch(void* const* d_in, const int* in_sizes, int n_in,
                              void* d_out, int out_size) {
    const float* X     = (const float*)d_in[0];
    const float* Y     = (const float*)d_in[1];
    const float* Wq    = (const float*)d_in[2];
    const float* bq    = (const float*)d_in[3];
    const float* Wk    = (const float*)d_in[4];
    const float* bk    = (const float*)d_in[5];
    const float* Wv    = (const float*)d_in[6];
    const float* bv    = (const float*)d_in[7];
    const float* nullk = (const float*)d_in[8];
    const float* g0    = (const float*)d_in[9];
    const float* b0    = (const float*)d_in[10];
    const float* g0kv  = (const float*)d_in[11];
    const float* b0kv  = (const float*)d_in[12];
    const float* g1    = (const float*)d_in[13];
    const float* b1    = (const float*)d_in[14];
    const float* W1    = (const float*)d_in[15];
    const float* bf1   = (const float*)d_in[16];
    const float* W2    = (const float*)d_in[17];
    const float* bf2   = (const float*)d_in[18];
    float* out = (float*)d_out;

    __half *Xn, *Yn, *Hr, *Hid, *Wqt, *Wkvt, *W1t, *W2t;
    float *Qp, *KVp, *Hres;
    cudaGetSymbolAddress((void**)&Xn,   g_Xn16);
    cudaGetSymbolAddress((void**)&Yn,   g_Yn16);
    cudaGetSymbolAddress((void**)&Hr,   g_Hr16);
    cudaGetSymbolAddress((void**)&Hid,  g_Hid16);
    cudaGetSymbolAddress((void**)&Qp,   g_Qp);
    cudaGetSymbolAddress((void**)&KVp,  g_KVp);
    cudaGetSymbolAddress((void**)&Hres, g_Hres);
    cudaGetSymbolAddress((void**)&Wqt,  g_Wqt16);
    cudaGetSymbolAddress((void**)&Wkvt, g_Wkvt16);
    cudaGetSymbolAddress((void**)&W1t,  g_W1t16);
    cudaGetSymbolAddress((void**)&W2t,  g_W2t16);

    const int gemm_smem = 3 * STAGE_BYTES;  // 49152
    const int attn_smem = (128 * 64 + 64 * 64) * (int)sizeof(float) + 64 * 32 * 4;
    cudaFuncSetAttribute(gemm_h<false, false>,
                         cudaFuncAttributeMaxDynamicSharedMemorySize, gemm_smem);
    cudaFuncSetAttribute(gemm_h<true, false>,
                         cudaFuncAttributeMaxDynamicSharedMemorySize, gemm_smem);
    cudaFuncSetAttribute(gemm_h<false, true>,
                         cudaFuncAttributeMaxDynamicSharedMemorySize, gemm_smem);
    cudaFuncSetAttribute(attn_kernel,
                         cudaFuncAttributeMaxDynamicSharedMemorySize, attn_smem);

    // weight transposes -> fp16 permuted; Wk|Wv fused
    transpose16_kernel<<<dim3(cfg::DC / 32, cfg::DC / 32), 256>>>(
        Wq, (__half2*)Wqt, cfg::DC, cfg::DC);
    transpose16_kernel<<<dim3(cfg::DC / 32, cfg::DC / 32), 256>>>(
        Wk, (__half2*)Wkvt, cfg::DC, cfg::DC);
    transpose16_kernel<<<dim3(cfg::DC / 32, cfg::DC / 32), 256>>>(
        Wv, (__half2*)(Wkvt + (size_t)cfg::DC * cfg::DC), cfg::DC, cfg::DC);
    transpose16_kernel<<<dim3(cfg::DFF / 32, cfg::DC / 32), 256>>>(
        W1, (__half2*)W1t, cfg::DC, cfg::DFF);
    transpose16_kernel<<<dim3(cfg::DC / 32, cfg::DFF / 32), 256>>>(
        W2, (__half2*)W2t, cfg::DFF, cfg::DC);

    ln_kernel<<<cfg::MR, 256>>>(X, g0, b0, (__half2*)Xn);
    ln_kernel<<<cfg::MR, 256>>>(Y, g0kv, b0kv, (__half2*)Yn);

    // Q = Xn @ Wq + bq   [4096,1024]
    gemm_h<false, false><<<dim3(cfg::DC / 128, cfg::MR / 128), 256, gemm_smem>>>(
        Xn, Wqt, bq, bq, 1 << 30, Qp, nullptr, cfg::MR, cfg::DC, cfg::DC);
    // KV = Yn @ [Wk|Wv] + [bk|bv]  [4096,2048]
    gemm_h<false, false><<<dim3(2 * cfg::DC / 128, cfg::MR / 128), 256, gemm_smem>>>(
        Yn, Wkvt, bk, bv, cfg::DC, KVp, nullptr, cfg::MR, 2 * cfg::DC, cfg::DC);

    attn_kernel<<<dim3(cfg::NQC / 128, 16, cfg::BB), 256, attn_smem>>>(
        Qp, KVp, nullk, X, Hres);

    ln_kernel<<<cfg::MR, 256>>>(Hres, g1, b1, (__half2*)Hr);

    // FFN1: Hid = gelu(Hr @ W1 + bf1) -> fp16 permuted   [4096,4096]
    gemm_h<true, false><<<dim3(cfg::DFF / 128, cfg::MR / 128), 256, gemm_smem>>>(
        Hr, W1t, bf1, bf1, 1 << 30, Hid, nullptr, cfg::MR, cfg::DFF, cfg::DC);
    // FFN2: out = Hid @ W2 + bf2 + Hres   [4096,1024]
    gemm_h<false, true><<<dim3(cfg::DC / 128, cfg::MR / 128), 256, gemm_smem>>>(
        Hid, W2t, bf2, bf2, 1 << 30, out, Hres, cfg::MR, cfg::DC, cfg::DFF);
}

// round 7
// speedup vs baseline: 1.8205x; 1.1151x over previous
#include <cuda_runtime.h>
#include <cuda_fp16.h>
#include <cuda_bf16.h>
#include <cstdint>
#include <math.h>

// ---------------------------------------------------------------------------
// MAB block: B=2, NQ=NKV=2048, D=1024, H=16, DH=64
// fp16 mma.sync m16n8k16 everywhere (k-pair-permuted operands):
// GEMMs (cp.async 3-stage) + flash attention (fp16 QK^T, bf16 PV)
// ---------------------------------------------------------------------------

namespace cfg {
constexpr int BB   = 2;
constexpr int NQC  = 2048;
constexpr int NKVC = 2048;
constexpr int DC   = 1024;
constexpr int DHC  = 64;
constexpr int MR   = BB * NQC;   // 4096 rows
constexpr int DFF  = 4 * DC;     // 4096
}

// scratch (device globals; allocation APIs are forbidden)
__device__ __half g_Xn16[cfg::MR * cfg::DC];
__device__ __half g_Yn16[cfg::MR * cfg::DC];
__device__ __half g_Hr16[cfg::MR * cfg::DC];
__device__ __half g_Hid16[cfg::MR * cfg::DFF];
__device__ __half g_Q16[cfg::MR * cfg::DC];
__device__ __half g_KV16[cfg::MR * 2 * cfg::DC];  // fused K|V fp16 perm, stride 2048
__device__ __half g_nk16[cfg::DC];
__device__ float  g_Hres[cfg::MR * cfg::DC];
// transposed fp16 (k-pair-permuted) weights
__device__ __half g_Wqt16[cfg::DC * cfg::DC];
__device__ __half g_Wkvt16[2 * cfg::DC * cfg::DC];
__device__ __half g_W1t16[cfg::DC * cfg::DFF];
__device__ __half g_W2t16[cfg::DFF * cfg::DC];

// ---------------------------------------------------------------------------
// helpers
// ---------------------------------------------------------------------------
// pair permutation within a 16-pair (32-element) k-group (self-inverse)
__device__ __host__ __forceinline__ int permp(int p) { return ((p & 3) << 2) | (p >> 2); }

__device__ __forceinline__ uint32_t smem_u32(const void* p) {
    uint32_t a;
    asm("{ .reg .u64 t; cvta.to.shared.u64 t, %1; cvt.u32.u64 %0, t; }"
        : "=r"(a) : "l"(p));
    return a;
}

__device__ __forceinline__ void cp_async16(uint32_t smem_addr, const void* gptr) {
    asm volatile("cp.async.cg.shared.global [%0], [%1], 16;\n"
                 :: "r"(smem_addr), "l"(gptr));
}
__device__ __forceinline__ void cp_commit() {
    asm volatile("cp.async.commit_group;\n" ::: "memory");
}
template <int N>
__device__ __forceinline__ void cp_wait() {
    asm volatile("cp.async.wait_group %0;\n" :: "n"(N) : "memory");
}

__device__ __forceinline__ void mma_f16(float d[4], unsigned a0, unsigned a1,
                                        unsigned a2, unsigned a3,
                                        unsigned b0, unsigned b1) {
    asm volatile(
        "mma.sync.aligned.m16n8k16.row.col.f32.f16.f16.f32 "
        "{%0,%1,%2,%3},{%4,%5,%6,%7},{%8,%9},{%0,%1,%2,%3};"
        : "+f"(d[0]), "+f"(d[1]), "+f"(d[2]), "+f"(d[3])
        : "r"(a0), "r"(a1), "r"(a2), "r"(a3), "r"(b0), "r"(b1));
}
__device__ __forceinline__ void mma_bf16(float d[4], const unsigned a[4], const unsigned b[2]) {
    asm volatile(
        "mma.sync.aligned.m16n8k16.row.col.f32.bf16.bf16.f32 "
        "{%0,%1,%2,%3},{%4,%5,%6,%7},{%8,%9},{%0,%1,%2,%3};"
        : "+f"(d[0]), "+f"(d[1]), "+f"(d[2]), "+f"(d[3])
        : "r"(a[0]), "r"(a[1]), "r"(a[2]), "r"(a[3]), "r"(b[0]), "r"(b[1]));
}

// ---------------------------------------------------------------------------
// LayerNorm: one block/row, 256 threads, D=1024. Output fp16 k-pair-permuted.
// ---------------------------------------------------------------------------
__global__ __launch_bounds__(256) void ln_kernel(const float* __restrict__ x,
                                                 const float* __restrict__ gamma,
                                                 const float* __restrict__ beta,
                                                 __half2* __restrict__ y) {
    const int row = blockIdx.x;
    const int tid = threadIdx.x;
    const float4 v = reinterpret_cast<const float4*>(x + (size_t)row * cfg::DC)[tid];
    float s  = v.x + v.y + v.z + v.w;
    float sq = v.x * v.x + v.y * v.y + v.z * v.z + v.w * v.w;
#pragma unroll
    for (int o = 16; o; o >>= 1) {
        s  += __shfl_xor_sync(0xffffffffu, s, o);
        sq += __shfl_xor_sync(0xffffffffu, sq, o);
    }
    __shared__ float ssum[8], ssq[8];
    if ((tid & 31) == 0) { ssum[tid >> 5] = s; ssq[tid >> 5] = sq; }
    __syncthreads();
    float ts = 0.f, tq = 0.f;
#pragma unroll
    for (int i = 0; i < 8; i++) { ts += ssum[i]; tq += ssq[i]; }
    const float mu  = ts * (1.f / cfg::DC);
    const float var = tq * (1.f / cfg::DC) - mu * mu;
    const float rs  = rsqrtf(var + 1e-5f);
    const float4 g4 = reinterpret_cast<const float4*>(gamma)[tid];
    const float4 b4 = reinterpret_cast<const float4*>(beta)[tid];
    float4 o;
    o.x = (v.x - mu) * rs * g4.x + b4.x;
    o.y = (v.y - mu) * rs * g4.y + b4.y;
    o.z = (v.z - mu) * rs * g4.z + b4.z;
    o.w = (v.w - mu) * rs * g4.w + b4.w;
    const int kp = 2 * tid;
    const int t  = kp >> 4;
    const int p0 = kp & 15;
    __half2* yr = y + (size_t)row * (cfg::DC / 2) + (t << 4);
    yr[permp(p0)]     = __floats2half2_rn(o.x, o.y);
    yr[permp(p0 + 1)] = __floats2half2_rn(o.z, o.w);
}

// ---------------------------------------------------------------------------
// Weight transpose: W[K][N] -> Wt16[N][K] fp16, k-pair-permuted.
// ---------------------------------------------------------------------------
__global__ __launch_bounds__(256) void transpose16_kernel(const float* __restrict__ W,
                                                          __half2* __restrict__ Wt,
                                                          int K, int N) {
    __shared__ float t[32][33];
    const int k0 = blockIdx.y * 32, n0 = blockIdx.x * 32;
    const int tx = threadIdx.x & 31, ty = threadIdx.x >> 5;
#pragma unroll
    for (int j = 0; j < 4; j++)
        t[ty + j * 8][tx] = W[(size_t)(k0 + ty + j * 8) * N + n0 + tx];
    __syncthreads();
    const int nl = threadIdx.x >> 3;
    const int pb = threadIdx.x & 7;
    __half2* outr = Wt + (((size_t)(n0 + nl) * K + k0) >> 1);
#pragma unroll
    for (int q = 0; q < 2; q++) {
        const int p = pb + q * 8;
        outr[permp(p)] = __floats2half2_rn(t[2 * p][nl], t[2 * p + 1][nl]);
    }
}

// null_k -> fp16 permuted (one block, 256 threads, 512 pairs)
__global__ __launch_bounds__(256) void nk16_kernel(const float* __restrict__ nk,
                                                   __half2* __restrict__ nk16) {
    const int tid = threadIdx.x;
#pragma unroll
    for (int q = 0; q < 2; q++) {
        const int p = tid + q * 256;           // logical pair 0..511
        const int grp = p >> 4;
        nk16[(grp << 4) + permp(p & 15)] =
            __floats2half2_rn(nk[2 * p], nk[2 * p + 1]);
    }
}

// ---------------------------------------------------------------------------
// fp16 GEMM: C[M,N] = act(A[M,K] @ Wt[N,K]^T + bias) (+ res)
// OMODE: 0 = fp32 out, 1 = fp16 permuted out, 2 = fp16 permuted + gelu
// ---------------------------------------------------------------------------
__device__ __forceinline__ float gelu_exact(float x) {
    return 0.5f * x * (1.f + erff(x * 0.70710678118654752f));
}

constexpr int STAGE_BYTES = 16384;

template <int OMODE, bool RES>
__global__ __launch_bounds__(256, 2) void gemm_h(const __half* __restrict__ A,
                                                 const __half* __restrict__ Wt,
                                                 const float* __restrict__ bias1,
                                                 const float* __restrict__ bias2,
                                                 int split,
                                                 void* __restrict__ Cout,
                                                 const float* __restrict__ res,
                                                 int M, int N, int K) {
    extern __shared__ char smc[];

    const int tid  = threadIdx.x;
    const int lane = tid & 31;
    const int warp = tid >> 5;
    const int g = lane >> 2, c = lane & 3;
    const int wm = (warp >> 2) * 64;
    const int wn = (warp & 3) * 32;
    const int bm = blockIdx.y * 128;
    const int bn = blockIdx.x * 128;

    const int arow = tid >> 1;
    const int ach  = (tid & 1) * 2;
    const __half* Ag = A  + (size_t)(bm + arow) * K + ach * 8;
    const __half* Bg = Wt + (size_t)(bn + arow) * K + ach * 8;
    const uint32_t sa = smem_u32(smc) + (uint32_t)(arow * 64);
    const uint32_t sb = sa + 128 * 64;
    const uint32_t d0 = (uint32_t)(((ach    ) ^ (arow & 3)) * 16);
    const uint32_t d1 = (uint32_t)(((ach + 1) ^ (arow & 3)) * 16);

    float acc[4][4][4];
#pragma unroll
    for (int mt = 0; mt < 4; mt++)
#pragma unroll
        for (int nt = 0; nt < 4; nt++)
#pragma unroll
            for (int i = 0; i < 4; i++) acc[mt][nt][i] = 0.f;

    const int KT = K >> 5;

    auto load_stage = [&](int kt, int s) {
        const uint32_t st = (uint32_t)(s * STAGE_BYTES);
        const __half* ag = Ag + kt * 32;
        const __half* bg = Bg + kt * 32;
        cp_async16(sa + st + d0, ag);
        cp_async16(sa + st + d1, ag + 8);
        cp_async16(sb + st + d0, bg);
        cp_async16(sb + st + d1, bg + 8);
    };

    load_stage(0, 0); cp_commit();
    if (KT > 1) load_stage(1, 1);
    cp_commit();

    const uint32_t choff = (uint32_t)((c ^ (g & 3)) * 16);

    for (int kt = 0; kt < KT; kt++) {
        cp_wait<1>();
        __syncthreads();

        if (kt + 2 < KT) load_stage(kt + 2, (kt + 2) % 3);
        cp_commit();

        const char* Ab = smc + (kt % 3) * STAGE_BYTES;
        const char* Bb = Ab + 128 * 64;

        uint4 bv[4];
#pragma unroll
        for (int nt = 0; nt < 4; nt++)
            bv[nt] = *(const uint4*)(Bb + (wn + nt * 8 + g) * 64 + choff);
#pragma unroll
        for (int mt = 0; mt < 4; mt++) {
            const char* ap = Ab + (wm + mt * 16 + g) * 64 + choff;
            const uint4 lo = *(const uint4*)ap;
            const uint4 hi = *(const uint4*)(ap + 8 * 64);
#pragma unroll
            for (int nt = 0; nt < 4; nt++) {
                mma_f16(acc[mt][nt], lo.x, hi.x, lo.y, hi.y, bv[nt].x, bv[nt].y);
                mma_f16(acc[mt][nt], lo.z, hi.z, lo.w, hi.w, bv[nt].z, bv[nt].w);
            }
        }
    }

    // epilogue
    if (OMODE == 0) {
        float* C = (float*)Cout;
#pragma unroll
        for (int nt = 0; nt < 4; nt++) {
            const int col = bn + wn + nt * 8 + 2 * c;
            const float b0v = (col < split) ? bias1[col] : bias2[col - split];
            const float b1v = (col + 1 < split) ? bias1[col + 1] : bias2[col + 1 - split];
#pragma unroll
            for (int mt = 0; mt < 4; mt++) {
                const int r0 = bm + wm + mt * 16 + g;
                float x0 = acc[mt][nt][0] + b0v;
                float x1 = acc[mt][nt][1] + b1v;
                float x2 = acc[mt][nt][2] + b0v;
                float x3 = acc[mt][nt][3] + b1v;
                if (RES) {
                    const float2 r0v = *(const float2*)(res + (size_t)r0 * N + col);
                    const float2 r1v = *(const float2*)(res + (size_t)(r0 + 8) * N + col);
                    x0 += r0v.x; x1 += r0v.y; x2 += r1v.x; x3 += r1v.y;
                }
                *(float2*)(C + (size_t)r0 * N + col)       = make_float2(x0, x1);
                *(float2*)(C + (size_t)(r0 + 8) * N + col) = make_float2(x2, x3);
            }
        }
    } else {
        __half2* C = (__half2*)Cout;
        const int NH = N >> 1;
#pragma unroll
        for (int nt = 0; nt < 4; nt++) {
            const int n = bn + wn + nt * 8 + 2 * c;
            const float b0v = (n < split) ? bias1[n] : bias2[n - split];
            const float b1v = (n + 1 < split) ? bias1[n + 1] : bias2[n + 1 - split];
            const int h2off = ((n >> 5) << 4) + permp((n >> 1) & 15);
#pragma unroll
            for (int mt = 0; mt < 4; mt++) {
                const int r0 = bm + wm + mt * 16 + g;
                float x0 = acc[mt][nt][0] + b0v;
                float x1 = acc[mt][nt][1] + b1v;
                float x2 = acc[mt][nt][2] + b0v;
                float x3 = acc[mt][nt][3] + b1v;
                if (OMODE == 2) {
                    x0 = gelu_exact(x0); x1 = gelu_exact(x1);
                    x2 = gelu_exact(x2); x3 = gelu_exact(x3);
                }
                C[(size_t)r0 * NH + h2off]       = __floats2half2_rn(x0, x1);
                C[(size_t)(r0 + 8) * NH + h2off] = __floats2half2_rn(x2, x3);
            }
        }
    }
}

// ---------------------------------------------------------------------------
// Flash attention (fp16 QK^T): grid (NQ/128, H, B), 256 threads.
// Q, KV fp16 k-pair-permuted; V converted to bf16 transposed for PV.
// ---------------------------------------------------------------------------
__global__ __launch_bounds__(256, 2) void attn_kernel(const __half* __restrict__ Q,
                                                      const __half* __restrict__ KV,
                                                      const __half* __restrict__ nk16,
                                                      const float* __restrict__ X,
                                                      float* __restrict__ Hres) {
    extern __shared__ char smraw[];
    char* Qs = smraw;                         // 128 rows * 128B = 16384
    char* Ks = Qs + 128 * 128;                // 64 rows * 128B = 8192
    unsigned* VsT = (unsigned*)(Ks + 64 * 128);  // [dh][keypair] bf16x2, 8192

    const int b = blockIdx.z, h = blockIdx.y;
    const int q0 = blockIdx.x * 128;
    const int tid = threadIdx.x, lane = tid & 31, warp = tid >> 5;
    const int g = lane >> 2, c = lane & 3;
    const int R0 = warp * 16;
    const int qrowbase = b * cfg::NQC + q0;
    const int hc = h * cfg::DHC;

    // Q tile: 128 rows x 64 halves (verbatim copy, chunk-swizzled)
    {
        const int row = tid >> 1;
        const int c0 = (tid & 1) * 4;
        const __half* qr = Q + (size_t)(qrowbase + row) * cfg::DC + hc;
#pragma unroll
        for (int j = 0; j < 4; j++) {
            const int j2 = c0 + j;
            const uint4 v = *(const uint4*)(qr + j2 * 8);
            const int phys = (j2 & 4) | ((j2 & 3) ^ (row & 3));
            *(uint4*)(Qs + row * 128 + phys * 16) = v;
        }
    }

    float m_lo = -1e30f, m_hi = -1e30f;
    float l_lo = 0.f, l_hi = 0.f;
    float o[8][4];
#pragma unroll
    for (int nt = 0; nt < 8; nt++)
#pragma unroll
        for (int i = 0; i < 4; i++) o[nt][i] = 0.f;

    const float scale = 0.03125f;  // 1/sqrt(1024)
    const int NTILES = 33;         // ceil(2049/64)

    for (int kt = 0; kt < NTILES; kt++) {
        const int kb = kt * 64;
        __syncthreads();
        // K,V tile: 64 rows; 4 threads/row, 2 chunks each for K and V
        {
            const int row = tid >> 2;
            const int cc0 = (tid & 3) * 2;
            const int key = kb + row;
            const __half* ksrc = nullptr;
            const __half* vsrc = nullptr;
            if (key < cfg::NKVC) {
                const __half* base = KV + (size_t)(b * cfg::NKVC + key) * 2048 + hc;
                ksrc = base;
                vsrc = base + cfg::DC;
            } else if (key == cfg::NKVC) {
                ksrc = nk16 + hc;
            }
            const int kp   = row >> 1;
            const int kpar = row & 1;
#pragma unroll
            for (int j = 0; j < 2; j++) {
                const int j2 = cc0 + j;
                const int phys = (j2 & 4) | ((j2 & 3) ^ (row & 3));
                uint4 kvv = make_uint4(0, 0, 0, 0);
                if (ksrc) kvv = *(const uint4*)(ksrc + j2 * 8);
                *(uint4*)(Ks + row * 128 + phys * 16) = kvv;

                uint4 vvv = make_uint4(0, 0, 0, 0);
                if (vsrc) vvv = *(const uint4*)(vsrc + j2 * 8);
                const __half2* ph = (const __half2*)&vvv;
                const int grp = (j2 >> 2) * 32;
                const int jj = j2 & 3;
#pragma unroll
                for (int r = 0; r < 4; r++) {
                    const float2 f = __half22float2(ph[r]);
                    const int dh = grp + 2 * ((r << 2) | jj);
                    const int i0 = dh * 32 + (kp ^ ((dh & 7) << 2));
                    const int i1 = (dh + 1) * 32 + (kp ^ (((dh + 1) & 7) << 2));
                    ((__nv_bfloat16*)&VsT[i0])[kpar] = __float2bfloat16(f.x);
                    ((__nv_bfloat16*)&VsT[i1])[kpar] = __float2bfloat16(f.y);
                }
            }
        }
        __syncthreads();

        // S = Q K^T (fp16 m16n8k16)
        float s[8][4];
#pragma unroll
        for (int nt = 0; nt < 8; nt++)
#pragma unroll
            for (int i = 0; i < 4; i++) s[nt][i] = 0.f;
#pragma unroll
        for (int kc = 0; kc < 2; kc++) {
            const char* qrow = Qs + (R0 + g) * 128 + kc * 64;
            const int qsw = (c ^ (g & 3)) * 16;
            const uint4 lo = *(const uint4*)(qrow + qsw);
            const uint4 hi = *(const uint4*)(qrow + 8 * 128 + qsw);
#pragma unroll
            for (int nt = 0; nt < 8; nt++) {
                const int kr = nt * 8 + g;
                const uint4 bv = *(const uint4*)(Ks + kr * 128 + kc * 64 +
                                                 ((c ^ (kr & 3)) * 16));
                mma_f16(s[nt], lo.x, hi.x, lo.y, hi.y, bv.x, bv.y);
                mma_f16(s[nt], lo.z, hi.z, lo.w, hi.w, bv.z, bv.w);
            }
        }
#pragma unroll
        for (int nt = 0; nt < 8; nt++)
#pragma unroll
            for (int i = 0; i < 4; i++) s[nt][i] *= scale;
        if (kb + 64 > cfg::NKVC + 1) {
#pragma unroll
            for (int nt = 0; nt < 8; nt++) {
                const int col0 = kb + nt * 8 + 2 * c;
                if (col0 > cfg::NKVC)     { s[nt][0] = -1e30f; s[nt][2] = -1e30f; }
                if (col0 + 1 > cfg::NKVC) { s[nt][1] = -1e30f; s[nt][3] = -1e30f; }
            }
        }
        float rmax_lo = -1e30f, rmax_hi = -1e30f;
#pragma unroll
        for (int nt = 0; nt < 8; nt++) {
            rmax_lo = fmaxf(rmax_lo, fmaxf(s[nt][0], s[nt][1]));
            rmax_hi = fmaxf(rmax_hi, fmaxf(s[nt][2], s[nt][3]));
        }
        rmax_lo = fmaxf(rmax_lo, __shfl_xor_sync(0xffffffffu, rmax_lo, 1));
        rmax_lo = fmaxf(rmax_lo, __shfl_xor_sync(0xffffffffu, rmax_lo, 2));
        rmax_hi = fmaxf(rmax_hi, __shfl_xor_sync(0xffffffffu, rmax_hi, 1));
        rmax_hi = fmaxf(rmax_hi, __shfl_xor_sync(0xffffffffu, rmax_hi, 2));
        const float mn_lo = fmaxf(m_lo, rmax_lo);
        const float mn_hi = fmaxf(m_hi, rmax_hi);
        const float alpha_lo = __expf(m_lo - mn_lo);
        const float alpha_hi = __expf(m_hi - mn_hi);
        m_lo = mn_lo; m_hi = mn_hi;

        float rs_lo = 0.f, rs_hi = 0.f;
        unsigned pfrag[4][4];
#pragma unroll
        for (int t = 0; t < 4; t++) {
            const float p00 = __expf(s[2 * t][0] - m_lo);
            const float p01 = __expf(s[2 * t][1] - m_lo);
            const float p10 = __expf(s[2 * t][2] - m_hi);
            const float p11 = __expf(s[2 * t][3] - m_hi);
            const float p20 = __expf(s[2 * t + 1][0] - m_lo);
            const float p21 = __expf(s[2 * t + 1][1] - m_lo);
            const float p30 = __expf(s[2 * t + 1][2] - m_hi);
            const float p31 = __expf(s[2 * t + 1][3] - m_hi);
            rs_lo += p00 + p01 + p20 + p21;
            rs_hi += p10 + p11 + p30 + p31;
            __nv_bfloat162 t0 = __floats2bfloat162_rn(p00, p01);
            __nv_bfloat162 t1 = __floats2bfloat162_rn(p10, p11);
            __nv_bfloat162 t2 = __floats2bfloat162_rn(p20, p21);
            __nv_bfloat162 t3 = __floats2bfloat162_rn(p30, p31);
            pfrag[t][0] = *(unsigned*)&t0;
            pfrag[t][1] = *(unsigned*)&t1;
            pfrag[t][2] = *(unsigned*)&t2;
            pfrag[t][3] = *(unsigned*)&t3;
        }
        rs_lo += __shfl_xor_sync(0xffffffffu, rs_lo, 1);
        rs_lo += __shfl_xor_sync(0xffffffffu, rs_lo, 2);
        rs_hi += __shfl_xor_sync(0xffffffffu, rs_hi, 1);
        rs_hi += __shfl_xor_sync(0xffffffffu, rs_hi, 2);
        l_lo = l_lo * alpha_lo + rs_lo;
        l_hi = l_hi * alpha_hi + rs_hi;
#pragma unroll
        for (int nt = 0; nt < 8; nt++) {
            o[nt][0] *= alpha_lo; o[nt][1] *= alpha_lo;
            o[nt][2] *= alpha_hi; o[nt][3] *= alpha_hi;
        }
#pragma unroll
        for (int t = 0; t < 4; t++) {
#pragma unroll
            for (int nt = 0; nt < 8; nt++) {
                const int dh = nt * 8 + g;
                unsigned bb[2];
                bb[0] = VsT[dh * 32 + ((8 * t + c) ^ ((dh & 7) << 2))];
                bb[1] = VsT[dh * 32 + ((8 * t + c + 4) ^ ((dh & 7) << 2))];
                mma_bf16(o[nt], pfrag[t], bb);
            }
        }
    }

    const float il_lo = 1.f / l_lo;
    const float il_hi = 1.f / l_hi;
    const int row  = qrowbase + R0 + g;
    const int row2 = row + 8;
#pragma unroll
    for (int nt = 0; nt < 8; nt++) {
        const int col = hc + nt * 8 + 2 * c;
        const float2 x0 = *(const float2*)(X + (size_t)row * cfg::DC + col);
        const float2 x1 = *(const float2*)(X + (size_t)row2 * cfg::DC + col);
        *(float2*)(Hres + (size_t)row * cfg::DC + col) =
            make_float2(o[nt][0] * il_lo + x0.x, o[nt][1] * il_lo + x0.y);
        *(float2*)(Hres + (size_t)row2 * cfg::DC + col) =
            make_float2(o[nt][2] * il_hi + x1.x, o[nt][3] * il_hi + x1.y);
    }
}

// ---------------------------------------------------------------------------
extern "C" void kernel_launch(void* const* d_in, const int* in_sizes, int n_in,
                              void* d_out, int out_size) {
    const float* X     = (const float*)d_in[0];
    const float* Y     = (const float*)d_in[1];
    const float* Wq    = (const float*)d_in[2];
    const float* bq    = (const float*)d_in[3];
    const float* Wk    = (const float*)d_in[4];
    const float* bk    = (const float*)d_in[5];
    const float* Wv    = (const float*)d_in[6];
    const float* bv    = (const float*)d_in[7];
    const float* nullk = (const float*)d_in[8];
    const float* g0    = (const float*)d_in[9];
    const float* b0    = (const float*)d_in[10];
    const float* g0kv  = (const float*)d_in[11];
    const float* b0kv  = (const float*)d_in[12];
    const float* g1    = (const float*)d_in[13];
    const float* b1    = (const float*)d_in[14];
    const float* W1    = (const float*)d_in[15];
    const float* bf1   = (const float*)d_in[16];
    const float* W2    = (const float*)d_in[17];
    const float* bf2   = (const float*)d_in[18];
    float* out = (float*)d_out;

    __half *Xn, *Yn, *Hr, *Hid, *Q16, *KV16, *nk16, *Wqt, *Wkvt, *W1t, *W2t;
    float *Hres;
    cudaGetSymbolAddress((void**)&Xn,   g_Xn16);
    cudaGetSymbolAddress((void**)&Yn,   g_Yn16);
    cudaGetSymbolAddress((void**)&Hr,   g_Hr16);
    cudaGetSymbolAddress((void**)&Hid,  g_Hid16);
    cudaGetSymbolAddress((void**)&Q16,  g_Q16);
    cudaGetSymbolAddress((void**)&KV16, g_KV16);
    cudaGetSymbolAddress((void**)&nk16, g_nk16);
    cudaGetSymbolAddress((void**)&Hres, g_Hres);
    cudaGetSymbolAddress((void**)&Wqt,  g_Wqt16);
    cudaGetSymbolAddress((void**)&Wkvt, g_Wkvt16);
    cudaGetSymbolAddress((void**)&W1t,  g_W1t16);
    cudaGetSymbolAddress((void**)&W2t,  g_W2t16);

    const int gemm_smem = 3 * STAGE_BYTES;                       // 49152
    const int attn_smem = 128 * 128 + 64 * 128 + 64 * 32 * 4;    // 32768
    cudaFuncSetAttribute(gemm_h<1, false>,
                         cudaFuncAttributeMaxDynamicSharedMemorySize, gemm_smem);
    cudaFuncSetAttribute(gemm_h<2, false>,
                         cudaFuncAttributeMaxDynamicSharedMemorySize, gemm_smem);
    cudaFuncSetAttribute(gemm_h<0, true>,
                         cudaFuncAttributeMaxDynamicSharedMemorySize, gemm_smem);
    cudaFuncSetAttribute(attn_kernel,
                         cudaFuncAttributeMaxDynamicSharedMemorySize, attn_smem);

    // weight transposes -> fp16 permuted; Wk|Wv fused; null_k conversion
    transpose16_kernel<<<dim3(cfg::DC / 32, cfg::DC / 32), 256>>>(
        Wq, (__half2*)Wqt, cfg::DC, cfg::DC);
    transpose16_kernel<<<dim3(cfg::DC / 32, cfg::DC / 32), 256>>>(
        Wk, (__half2*)Wkvt, cfg::DC, cfg::DC);
    transpose16_kernel<<<dim3(cfg::DC / 32, cfg::DC / 32), 256>>>(
        Wv, (__half2*)(Wkvt + (size_t)cfg::DC * cfg::DC), cfg::DC, cfg::DC);
    transpose16_kernel<<<dim3(cfg::DFF / 32, cfg::DC / 32), 256>>>(
        W1, (__half2*)W1t, cfg::DC, cfg::DFF);
    transpose16_kernel<<<dim3(cfg::DC / 32, cfg::DFF / 32), 256>>>(
        W2, (__half2*)W2t, cfg::DFF, cfg::DC);
    nk16_kernel<<<1, 256>>>(nullk, (__half2*)nk16);

    ln_kernel<<<cfg::MR, 256>>>(X, g0, b0, (__half2*)Xn);
    ln_kernel<<<cfg::MR, 256>>>(Y, g0kv, b0kv, (__half2*)Yn);

    // Q = Xn @ Wq + bq -> fp16 perm   [4096,1024]
    gemm_h<1, false><<<dim3(cfg::DC / 128, cfg::MR / 128), 256, gemm_smem>>>(
        Xn, Wqt, bq, bq, 1 << 30, Q16, nullptr, cfg::MR, cfg::DC, cfg::DC);
    // KV = Yn @ [Wk|Wv] + [bk|bv] -> fp16 perm  [4096,2048]
    gemm_h<1, false><<<dim3(2 * cfg::DC / 128, cfg::MR / 128), 256, gemm_smem>>>(
        Yn, Wkvt, bk, bv, cfg::DC, KV16, nullptr, cfg::MR, 2 * cfg::DC, cfg::DC);

    attn_kernel<<<dim3(cfg::NQC / 128, 16, cfg::BB), 256, attn_smem>>>(
        Q16, KV16, nk16, X, Hres);

    ln_kernel<<<cfg::MR, 256>>>(Hres, g1, b1, (__half2*)Hr);

    // FFN1: Hid = gelu(Hr @ W1 + bf1) -> fp16 perm   [4096,4096]
    gemm_h<2, false><<<dim3(cfg::DFF / 128, cfg::MR / 128), 256, gemm_smem>>>(
        Hr, W1t, bf1, bf1, 1 << 30, Hid, nullptr, cfg::MR, cfg::DFF, cfg::DC);
    // FFN2: out = Hid @ W2 + bf2 + Hres   [4096,1024]
    gemm_h<0, true><<<dim3(cfg::DC / 128, cfg::MR / 128), 256, gemm_smem>>>(
        Hid, W2t, bf2, bf2, 1 << 30, out, Hres, cfg::MR, cfg::DC, cfg::DFF);
}

// round 8
// speedup vs baseline: 2.0295x; 1.1148x over previous
#include <cuda_runtime.h>
#include <cuda_fp16.h>
#include <cuda_bf16.h>
#include <cstdint>
#include <math.h>

// ---------------------------------------------------------------------------
// MAB block: B=2, NQ=NKV=2048, D=1024, H=16, DH=64
// fp16 mma.sync m16n8k16 everywhere; GEMMs: cp.async 4-stage;
// attention: cp.async 3-buffer KV ring, fp16 QK^T + fp16 PV (ldmatrix.trans V)
// ---------------------------------------------------------------------------

namespace cfg {
constexpr int BB   = 2;
constexpr int NQC  = 2048;
constexpr int NKVC = 2048;
constexpr int DC   = 1024;
constexpr int DHC  = 64;
constexpr int MR   = BB * NQC;   // 4096 rows
constexpr int DFF  = 4 * DC;     // 4096
}

// scratch (device globals; allocation APIs are forbidden)
__device__ __half g_Xn16[cfg::MR * cfg::DC];
__device__ __half g_Yn16[cfg::MR * cfg::DC];
__device__ __half g_Hr16[cfg::MR * cfg::DC];
__device__ __half g_Hid16[cfg::MR * cfg::DFF];
__device__ __half g_Q16[cfg::MR * cfg::DC];
__device__ __half g_KV16[cfg::MR * 2 * cfg::DC];  // fused K|V fp16 perm, stride 2048
__device__ __half g_nk16[cfg::DC];
__device__ __half g_zero16[1024];                 // zero-initialized
__device__ float  g_Hres[cfg::MR * cfg::DC];
// transposed fp16 (k-pair-permuted) weights
__device__ __half g_Wqt16[cfg::DC * cfg::DC];
__device__ __half g_Wkvt16[2 * cfg::DC * cfg::DC];
__device__ __half g_W1t16[cfg::DC * cfg::DFF];
__device__ __half g_W2t16[cfg::DFF * cfg::DC];

// ---------------------------------------------------------------------------
// helpers
// ---------------------------------------------------------------------------
__device__ __host__ __forceinline__ int permp(int p) { return ((p & 3) << 2) | (p >> 2); }

__device__ __forceinline__ uint32_t smem_u32(const void* p) {
    uint32_t a;
    asm("{ .reg .u64 t; cvta.to.shared.u64 t, %1; cvt.u32.u64 %0, t; }"
        : "=r"(a) : "l"(p));
    return a;
}

__device__ __forceinline__ void cp_async16(uint32_t smem_addr, const void* gptr) {
    asm volatile("cp.async.cg.shared.global [%0], [%1], 16;\n"
                 :: "r"(smem_addr), "l"(gptr));
}
__device__ __forceinline__ void cp_commit() {
    asm volatile("cp.async.commit_group;\n" ::: "memory");
}
template <int N>
__device__ __forceinline__ void cp_wait() {
    asm volatile("cp.async.wait_group %0;\n" :: "n"(N) : "memory");
}

__device__ __forceinline__ void mma_f16(float d[4], unsigned a0, unsigned a1,
                                        unsigned a2, unsigned a3,
                                        unsigned b0, unsigned b1) {
    asm volatile(
        "mma.sync.aligned.m16n8k16.row.col.f32.f16.f16.f32 "
        "{%0,%1,%2,%3},{%4,%5,%6,%7},{%8,%9},{%0,%1,%2,%3};"
        : "+f"(d[0]), "+f"(d[1]), "+f"(d[2]), "+f"(d[3])
        : "r"(a0), "r"(a1), "r"(a2), "r"(a3), "r"(b0), "r"(b1));
}

__device__ __forceinline__ void ldsm_x4_trans(uint32_t& r0, uint32_t& r1,
                                              uint32_t& r2, uint32_t& r3,
                                              uint32_t addr) {
    asm volatile(
        "ldmatrix.sync.aligned.m8n8.x4.trans.shared.b16 {%0,%1,%2,%3}, [%4];"
        : "=r"(r0), "=r"(r1), "=r"(r2), "=r"(r3) : "r"(addr));
}

// ---------------------------------------------------------------------------
// LayerNorm: one block/row, 256 threads, D=1024. Output fp16 k-pair-permuted.
// ---------------------------------------------------------------------------
__global__ __launch_bounds__(256) void ln_kernel(const float* __restrict__ x,
                                                 const float* __restrict__ gamma,
                                                 const float* __restrict__ beta,
                                                 __half2* __restrict__ y) {
    const int row = blockIdx.x;
    const int tid = threadIdx.x;
    const float4 v = reinterpret_cast<const float4*>(x + (size_t)row * cfg::DC)[tid];
    float s  = v.x + v.y + v.z + v.w;
    float sq = v.x * v.x + v.y * v.y + v.z * v.z + v.w * v.w;
#pragma unroll
    for (int o = 16; o; o >>= 1) {
        s  += __shfl_xor_sync(0xffffffffu, s, o);
        sq += __shfl_xor_sync(0xffffffffu, sq, o);
    }
    __shared__ float ssum[8], ssq[8];
    if ((tid & 31) == 0) { ssum[tid >> 5] = s; ssq[tid >> 5] = sq; }
    __syncthreads();
    float ts = 0.f, tq = 0.f;
#pragma unroll
    for (int i = 0; i < 8; i++) { ts += ssum[i]; tq += ssq[i]; }
    const float mu  = ts * (1.f / cfg::DC);
    const float var = tq * (1.f / cfg::DC) - mu * mu;
    const float rs  = rsqrtf(var + 1e-5f);
    const float4 g4 = reinterpret_cast<const float4*>(gamma)[tid];
    const float4 b4 = reinterpret_cast<const float4*>(beta)[tid];
    float4 o;
    o.x = (v.x - mu) * rs * g4.x + b4.x;
    o.y = (v.y - mu) * rs * g4.y + b4.y;
    o.z = (v.z - mu) * rs * g4.z + b4.z;
    o.w = (v.w - mu) * rs * g4.w + b4.w;
    const int kp = 2 * tid;
    const int t  = kp >> 4;
    const int p0 = kp & 15;
    __half2* yr = y + (size_t)row * (cfg::DC / 2) + (t << 4);
    yr[permp(p0)]     = __floats2half2_rn(o.x, o.y);
    yr[permp(p0 + 1)] = __floats2half2_rn(o.z, o.w);
}

// ---------------------------------------------------------------------------
// Weight transpose: W[K][N] -> Wt16[N][K] fp16, k-pair-permuted.
// ---------------------------------------------------------------------------
__global__ __launch_bounds__(256) void transpose16_kernel(const float* __restrict__ W,
                                                          __half2* __restrict__ Wt,
                                                          int K, int N) {
    __shared__ float t[32][33];
    const int k0 = blockIdx.y * 32, n0 = blockIdx.x * 32;
    const int tx = threadIdx.x & 31, ty = threadIdx.x >> 5;
#pragma unroll
    for (int j = 0; j < 4; j++)
        t[ty + j * 8][tx] = W[(size_t)(k0 + ty + j * 8) * N + n0 + tx];
    __syncthreads();
    const int nl = threadIdx.x >> 3;
    const int pb = threadIdx.x & 7;
    __half2* outr = Wt + (((size_t)(n0 + nl) * K + k0) >> 1);
#pragma unroll
    for (int q = 0; q < 2; q++) {
        const int p = pb + q * 8;
        outr[permp(p)] = __floats2half2_rn(t[2 * p][nl], t[2 * p + 1][nl]);
    }
}

// null_k -> fp16 permuted (one block, 256 threads, 512 pairs)
__global__ __launch_bounds__(256) void nk16_kernel(const float* __restrict__ nk,
                                                   __half2* __restrict__ nk16) {
    const int tid = threadIdx.x;
#pragma unroll
    for (int q = 0; q < 2; q++) {
        const int p = tid + q * 256;
        const int grp = p >> 4;
        nk16[(grp << 4) + permp(p & 15)] =
            __floats2half2_rn(nk[2 * p], nk[2 * p + 1]);
    }
}

// ---------------------------------------------------------------------------
// fp16 GEMM: C[M,N] = act(A[M,K] @ Wt[N,K]^T + bias) (+ res)
// OMODE: 0 = fp32 out, 1 = fp16 permuted out, 2 = fp16 permuted + gelu
// 4-stage cp.async ring, one __syncthreads per k-iter, 2 CTA/SM.
// ---------------------------------------------------------------------------
__device__ __forceinline__ float gelu_exact(float x) {
    return 0.5f * x * (1.f + erff(x * 0.70710678118654752f));
}

constexpr int STAGE_BYTES = 16384;
constexpr int GSTAGES = 4;

template <int OMODE, bool RES>
__global__ __launch_bounds__(256, 2) void gemm_h(const __half* __restrict__ A,
                                                 const __half* __restrict__ Wt,
                                                 const float* __restrict__ bias1,
                                                 const float* __restrict__ bias2,
                                                 int split,
                                                 void* __restrict__ Cout,
                                                 const float* __restrict__ res,
                                                 int M, int N, int K) {
    extern __shared__ char smc[];

    const int tid  = threadIdx.x;
    const int lane = tid & 31;
    const int warp = tid >> 5;
    const int g = lane >> 2, c = lane & 3;
    const int wm = (warp >> 2) * 64;
    const int wn = (warp & 3) * 32;
    const int bm = blockIdx.y * 128;
    const int bn = blockIdx.x * 128;

    const int arow = tid >> 1;
    const int ach  = (tid & 1) * 2;
    const __half* Ag = A  + (size_t)(bm + arow) * K + ach * 8;
    const __half* Bg = Wt + (size_t)(bn + arow) * K + ach * 8;
    const uint32_t sa = smem_u32(smc) + (uint32_t)(arow * 64);
    const uint32_t sb = sa + 128 * 64;
    const uint32_t d0 = (uint32_t)(((ach    ) ^ (arow & 3)) * 16);
    const uint32_t d1 = (uint32_t)(((ach + 1) ^ (arow & 3)) * 16);

    float acc[4][4][4];
#pragma unroll
    for (int mt = 0; mt < 4; mt++)
#pragma unroll
        for (int nt = 0; nt < 4; nt++)
#pragma unroll
            for (int i = 0; i < 4; i++) acc[mt][nt][i] = 0.f;

    const int KT = K >> 5;

    auto load_stage = [&](int kt, int s) {
        const uint32_t st = (uint32_t)(s * STAGE_BYTES);
        const __half* ag = Ag + kt * 32;
        const __half* bg = Bg + kt * 32;
        cp_async16(sa + st + d0, ag);
        cp_async16(sa + st + d1, ag + 8);
        cp_async16(sb + st + d0, bg);
        cp_async16(sb + st + d1, bg + 8);
    };

    load_stage(0, 0); cp_commit();
    load_stage(1, 1); cp_commit();
    load_stage(2, 2); cp_commit();

    const uint32_t choff = (uint32_t)((c ^ (g & 3)) * 16);

    for (int kt = 0; kt < KT; kt++) {
        cp_wait<GSTAGES - 2>();
        __syncthreads();

        if (kt + 3 < KT) load_stage(kt + 3, (kt + 3) % GSTAGES);
        cp_commit();

        const char* Ab = smc + (kt % GSTAGES) * STAGE_BYTES;
        const char* Bb = Ab + 128 * 64;

        uint4 bv[4];
#pragma unroll
        for (int nt = 0; nt < 4; nt++)
            bv[nt] = *(const uint4*)(Bb + (wn + nt * 8 + g) * 64 + choff);
#pragma unroll
        for (int mt = 0; mt < 4; mt++) {
            const char* ap = Ab + (wm + mt * 16 + g) * 64 + choff;
            const uint4 lo = *(const uint4*)ap;
            const uint4 hi = *(const uint4*)(ap + 8 * 64);
#pragma unroll
            for (int nt = 0; nt < 4; nt++) {
                mma_f16(acc[mt][nt], lo.x, hi.x, lo.y, hi.y, bv[nt].x, bv[nt].y);
                mma_f16(acc[mt][nt], lo.z, hi.z, lo.w, hi.w, bv[nt].z, bv[nt].w);
            }
        }
    }

    // epilogue
    if (OMODE == 0) {
        float* C = (float*)Cout;
#pragma unroll
        for (int nt = 0; nt < 4; nt++) {
            const int col = bn + wn + nt * 8 + 2 * c;
            const float b0v = (col < split) ? bias1[col] : bias2[col - split];
            const float b1v = (col + 1 < split) ? bias1[col + 1] : bias2[col + 1 - split];
#pragma unroll
            for (int mt = 0; mt < 4; mt++) {
                const int r0 = bm + wm + mt * 16 + g;
                float x0 = acc[mt][nt][0] + b0v;
                float x1 = acc[mt][nt][1] + b1v;
                float x2 = acc[mt][nt][2] + b0v;
                float x3 = acc[mt][nt][3] + b1v;
                if (RES) {
                    const float2 r0v = *(const float2*)(res + (size_t)r0 * N + col);
                    const float2 r1v = *(const float2*)(res + (size_t)(r0 + 8) * N + col);
                    x0 += r0v.x; x1 += r0v.y; x2 += r1v.x; x3 += r1v.y;
                }
                *(float2*)(C + (size_t)r0 * N + col)       = make_float2(x0, x1);
                *(float2*)(C + (size_t)(r0 + 8) * N + col) = make_float2(x2, x3);
            }
        }
    } else {
        __half2* C = (__half2*)Cout;
        const int NH = N >> 1;
#pragma unroll
        for (int nt = 0; nt < 4; nt++) {
            const int n = bn + wn + nt * 8 + 2 * c;
            const float b0v = (n < split) ? bias1[n] : bias2[n - split];
            const float b1v = (n + 1 < split) ? bias1[n + 1] : bias2[n + 1 - split];
            const int h2off = ((n >> 5) << 4) + permp((n >> 1) & 15);
#pragma unroll
            for (int mt = 0; mt < 4; mt++) {
                const int r0 = bm + wm + mt * 16 + g;
                float x0 = acc[mt][nt][0] + b0v;
                float x1 = acc[mt][nt][1] + b1v;
                float x2 = acc[mt][nt][2] + b0v;
                float x3 = acc[mt][nt][3] + b1v;
                if (OMODE == 2) {
                    x0 = gelu_exact(x0); x1 = gelu_exact(x1);
                    x2 = gelu_exact(x2); x3 = gelu_exact(x3);
                }
                C[(size_t)r0 * NH + h2off]       = __floats2half2_rn(x0, x1);
                C[(size_t)(r0 + 8) * NH + h2off] = __floats2half2_rn(x2, x3);
            }
        }
    }
}

// ---------------------------------------------------------------------------
// Flash attention: grid (NQ/128, H, B), 256 threads (8 warps x 16 q-rows).
// cp.async 3-buffer KV ring (one sync/tile); fp16 QK^T; fp16 PV with
// ldmatrix.x4.trans V fragments. O columns un-permuted at the final write.
// smem: Qs 16KB + 3 x (Ks 8KB | Vs 8KB) = 64KB.
// ---------------------------------------------------------------------------
__global__ __launch_bounds__(256, 2) void attn_kernel(const __half* __restrict__ Q,
                                                      const __half* __restrict__ KV,
                                                      const __half* __restrict__ nk16,
                                                      const __half* __restrict__ zero16,
                                                      const float* __restrict__ X,
                                                      float* __restrict__ Hres) {
    extern __shared__ char smraw[];
    char* Qs = smraw;                           // 128*128B
    const uint32_t smem0 = smem_u32(smraw);

    const int b = blockIdx.z, h = blockIdx.y;
    const int q0 = blockIdx.x * 128;
    const int tid = threadIdx.x, lane = tid & 31, warp = tid >> 5;
    const int g = lane >> 2, c = lane & 3;
    const int R0 = warp * 16;
    const int qrowbase = b * cfg::NQC + q0;
    const int hc = h * cfg::DHC;

    const int NTILES = 33;  // ceil(2049/64)

    // KV tile loader into ring buffer s (Ks then Vs)
    auto load_tile = [&](int kt, int s) {
        const uint32_t tb = smem0 + 16384u + (uint32_t)(s * 16384);
        const int row = tid >> 2;
        const int cc = tid & 3;
        const int key = kt * 64 + row;
        const __half* ksrc;
        const __half* vsrc;
        if (key < cfg::NKVC) {
            const __half* base = KV + (size_t)(b * cfg::NKVC + key) * 2048 + hc;
            ksrc = base;
            vsrc = base + cfg::DC;
        } else if (key == cfg::NKVC) {
            ksrc = nk16 + hc;
            vsrc = zero16;
        } else {
            ksrc = zero16;
            vsrc = zero16;
        }
#pragma unroll
        for (int jj = 0; jj < 2; jj++) {
            const int j = 2 * cc + jj;
            const int physK = (j & 4) | ((j & 3) ^ (row & 3));
            cp_async16(tb + (uint32_t)(row * 128 + physK * 16), ksrc + j * 8);
            const int physV = j ^ (row & 7);
            cp_async16(tb + 8192u + (uint32_t)(row * 128 + physV * 16), vsrc + j * 8);
        }
    };

    // prologue: Q tile + tile 0 in one group, tile 1 in another
    {
        const int row = tid >> 1;
        const int c0 = (tid & 1) * 4;
        const __half* qr = Q + (size_t)(qrowbase + row) * cfg::DC + hc;
#pragma unroll
        for (int j0 = 0; j0 < 4; j0++) {
            const int j = c0 + j0;
            const int phys = (j & 4) | ((j & 3) ^ (row & 3));
            cp_async16(smem0 + (uint32_t)(row * 128 + phys * 16), qr + j * 8);
        }
    }
    load_tile(0, 0); cp_commit();
    load_tile(1, 1); cp_commit();

    float m_lo = -1e30f, m_hi = -1e30f;
    float l_lo = 0.f, l_hi = 0.f;
    float o[8][4];
#pragma unroll
    for (int nt = 0; nt < 8; nt++)
#pragma unroll
        for (int i = 0; i < 4; i++) o[nt][i] = 0.f;

    const float scale = 0.03125f;  // 1/sqrt(1024)
    const int lrow7 = ((lane >> 3) & 1) * 8 + (lane & 7);
    const int cbsel = lane >> 4;
    const int qsw = (c ^ (g & 3)) * 16;

    for (int kt = 0; kt < NTILES; kt++) {
        const int kb = kt * 64;
        cp_wait<1>();
        __syncthreads();
        if (kt + 2 < NTILES) load_tile(kt + 2, (kt + 2) % 3);
        cp_commit();

        const char* Ks = smraw + 16384 + (kt % 3) * 16384;
        const uint32_t vsb = smem0 + 16384u + (uint32_t)((kt % 3) * 16384) + 8192u;

        // S = Q K^T (fp16 m16n8k16)
        float s[8][4];
#pragma unroll
        for (int nt = 0; nt < 8; nt++)
#pragma unroll
            for (int i = 0; i < 4; i++) s[nt][i] = 0.f;
#pragma unroll
        for (int kc = 0; kc < 2; kc++) {
            const char* qrow = Qs + (R0 + g) * 128 + kc * 64;
            const uint4 lo = *(const uint4*)(qrow + qsw);
            const uint4 hi = *(const uint4*)(qrow + 8 * 128 + qsw);
#pragma unroll
            for (int nt = 0; nt < 8; nt++) {
                const int kr = nt * 8 + g;
                const uint4 bv = *(const uint4*)(Ks + kr * 128 + kc * 64 +
                                                 ((c ^ (kr & 3)) * 16));
                mma_f16(s[nt], lo.x, hi.x, lo.y, hi.y, bv.x, bv.y);
                mma_f16(s[nt], lo.z, hi.z, lo.w, hi.w, bv.z, bv.w);
            }
        }
#pragma unroll
        for (int nt = 0; nt < 8; nt++)
#pragma unroll
            for (int i = 0; i < 4; i++) s[nt][i] *= scale;
        if (kb + 64 > cfg::NKVC + 1) {
#pragma unroll
            for (int nt = 0; nt < 8; nt++) {
                const int col0 = kb + nt * 8 + 2 * c;
                if (col0 > cfg::NKVC)     { s[nt][0] = -1e30f; s[nt][2] = -1e30f; }
                if (col0 + 1 > cfg::NKVC) { s[nt][1] = -1e30f; s[nt][3] = -1e30f; }
            }
        }
        float rmax_lo = -1e30f, rmax_hi = -1e30f;
#pragma unroll
        for (int nt = 0; nt < 8; nt++) {
            rmax_lo = fmaxf(rmax_lo, fmaxf(s[nt][0], s[nt][1]));
            rmax_hi = fmaxf(rmax_hi, fmaxf(s[nt][2], s[nt][3]));
        }
        rmax_lo = fmaxf(rmax_lo, __shfl_xor_sync(0xffffffffu, rmax_lo, 1));
        rmax_lo = fmaxf(rmax_lo, __shfl_xor_sync(0xffffffffu, rmax_lo, 2));
        rmax_hi = fmaxf(rmax_hi, __shfl_xor_sync(0xffffffffu, rmax_hi, 1));
        rmax_hi = fmaxf(rmax_hi, __shfl_xor_sync(0xffffffffu, rmax_hi, 2));
        const float mn_lo = fmaxf(m_lo, rmax_lo);
        const float mn_hi = fmaxf(m_hi, rmax_hi);
        const float alpha_lo = __expf(m_lo - mn_lo);
        const float alpha_hi = __expf(m_hi - mn_hi);
        m_lo = mn_lo; m_hi = mn_hi;

        float rs_lo = 0.f, rs_hi = 0.f;
        unsigned pfrag[4][4];
#pragma unroll
        for (int t = 0; t < 4; t++) {
            const float p00 = __expf(s[2 * t][0] - m_lo);
            const float p01 = __expf(s[2 * t][1] - m_lo);
            const float p10 = __expf(s[2 * t][2] - m_hi);
            const float p11 = __expf(s[2 * t][3] - m_hi);
            const float p20 = __expf(s[2 * t + 1][0] - m_lo);
            const float p21 = __expf(s[2 * t + 1][1] - m_lo);
            const float p30 = __expf(s[2 * t + 1][2] - m_hi);
            const float p31 = __expf(s[2 * t + 1][3] - m_hi);
            rs_lo += p00 + p01 + p20 + p21;
            rs_hi += p10 + p11 + p30 + p31;
            __half2 t0 = __floats2half2_rn(p00, p01);
            __half2 t1 = __floats2half2_rn(p10, p11);
            __half2 t2 = __floats2half2_rn(p20, p21);
            __half2 t3 = __floats2half2_rn(p30, p31);
            pfrag[t][0] = *(unsigned*)&t0;
            pfrag[t][1] = *(unsigned*)&t1;
            pfrag[t][2] = *(unsigned*)&t2;
            pfrag[t][3] = *(unsigned*)&t3;
        }
        rs_lo += __shfl_xor_sync(0xffffffffu, rs_lo, 1);
        rs_lo += __shfl_xor_sync(0xffffffffu, rs_lo, 2);
        rs_hi += __shfl_xor_sync(0xffffffffu, rs_hi, 1);
        rs_hi += __shfl_xor_sync(0xffffffffu, rs_hi, 2);
        l_lo = l_lo * alpha_lo + rs_lo;
        l_hi = l_hi * alpha_hi + rs_hi;
#pragma unroll
        for (int nt = 0; nt < 8; nt++) {
            o[nt][0] *= alpha_lo; o[nt][1] *= alpha_lo;
            o[nt][2] *= alpha_hi; o[nt][3] *= alpha_hi;
        }
        // O += P V : fp16 mma, V B-fragments via ldmatrix.x4.trans
#pragma unroll
        for (int t = 0; t < 4; t++) {
#pragma unroll
            for (int u = 0; u < 4; u++) {
                const int row = 16 * t + lrow7;
                const int cb = 2 * u + cbsel;
                const uint32_t addr = vsb + (uint32_t)(row * 128 + ((cb ^ (row & 7)) << 4));
                uint32_t b0, b1, b2, b3;
                ldsm_x4_trans(b0, b1, b2, b3, addr);
                mma_f16(o[2 * u], pfrag[t][0], pfrag[t][1], pfrag[t][2], pfrag[t][3],
                        b0, b1);
                mma_f16(o[2 * u + 1], pfrag[t][0], pfrag[t][1], pfrag[t][2], pfrag[t][3],
                        b2, b3);
            }
        }
    }

    // finalize: Hres = O/l + X  (un-permute O columns: phys pair -> logical)
    const float il_lo = 1.f / l_lo;
    const float il_hi = 1.f / l_hi;
    const int row  = qrowbase + R0 + g;
    const int row2 = row + 8;
#pragma unroll
    for (int nt = 0; nt < 8; nt++) {
        const int pp = nt * 4 + c;                       // phys pair in head
        const int lp = (pp & 16) | permp(pp & 15);       // logical pair
        const int col = hc + 2 * lp;
        const float2 x0 = *(const float2*)(X + (size_t)row * cfg::DC + col);
        const float2 x1 = *(const float2*)(X + (size_t)row2 * cfg::DC + col);
        *(float2*)(Hres + (size_t)row * cfg::DC + col) =
            make_float2(o[nt][0] * il_lo + x0.x, o[nt][1] * il_lo + x0.y);
        *(float2*)(Hres + (size_t)row2 * cfg::DC + col) =
            make_float2(o[nt][2] * il_hi + x1.x, o[nt][3] * il_hi + x1.y);
    }
}

// ---------------------------------------------------------------------------
extern "C" void kernel_launch(void* const* d_in, const int* in_sizes, int n_in,
                              void* d_out, int out_size) {
    const float* X     = (const float*)d_in[0];
    const float* Y     = (const float*)d_in[1];
    const float* Wq    = (const float*)d_in[2];
    const float* bq    = (const float*)d_in[3];
    const float* Wk    = (const float*)d_in[4];
    const float* bk    = (const float*)d_in[5];
    const float* Wv    = (const float*)d_in[6];
    const float* bv    = (const float*)d_in[7];
    const float* nullk = (const float*)d_in[8];
    const float* g0    = (const float*)d_in[9];
    const float* b0    = (const float*)d_in[10];
    const float* g0kv  = (const float*)d_in[11];
    const float* b0kv  = (const float*)d_in[12];
    const float* g1    = (const float*)d_in[13];
    const float* b1    = (const float*)d_in[14];
    const float* W1    = (const float*)d_in[15];
    const float* bf1   = (const float*)d_in[16];
    const float* W2    = (const float*)d_in[17];
    const float* bf2   = (const float*)d_in[18];
    float* out = (float*)d_out;

    __half *Xn, *Yn, *Hr, *Hid, *Q16, *KV16, *nk16, *zero16, *Wqt, *Wkvt, *W1t, *W2t;
    float *Hres;
    cudaGetSymbolAddress((void**)&Xn,     g_Xn16);
    cudaGetSymbolAddress((void**)&Yn,     g_Yn16);
    cudaGetSymbolAddress((void**)&Hr,     g_Hr16);
    cudaGetSymbolAddress((void**)&Hid,    g_Hid16);
    cudaGetSymbolAddress((void**)&Q16,    g_Q16);
    cudaGetSymbolAddress((void**)&KV16,   g_KV16);
    cudaGetSymbolAddress((void**)&nk16,   g_nk16);
    cudaGetSymbolAddress((void**)&zero16, g_zero16);
    cudaGetSymbolAddress((void**)&Hres,   g_Hres);
    cudaGetSymbolAddress((void**)&Wqt,    g_Wqt16);
    cudaGetSymbolAddress((void**)&Wkvt,   g_Wkvt16);
    cudaGetSymbolAddress((void**)&W1t,    g_W1t16);
    cudaGetSymbolAddress((void**)&W2t,    g_W2t16);

    const int gemm_smem = GSTAGES * STAGE_BYTES;          // 65536
    const int attn_smem = 16384 + 3 * 16384;              // 65536
    cudaFuncSetAttribute(gemm_h<1, false>,
                         cudaFuncAttributeMaxDynamicSharedMemorySize, gemm_smem);
    cudaFuncSetAttribute(gemm_h<2, false>,
                         cudaFuncAttributeMaxDynamicSharedMemorySize, gemm_smem);
    cudaFuncSetAttribute(gemm_h<0, true>,
                         cudaFuncAttributeMaxDynamicSharedMemorySize, gemm_smem);
    cudaFuncSetAttribute(attn_kernel,
                         cudaFuncAttributeMaxDynamicSharedMemorySize, attn_smem);

    transpose16_kernel<<<dim3(cfg::DC / 32, cfg::DC / 32), 256>>>(
        Wq, (__half2*)Wqt, cfg::DC, cfg::DC);
    transpose16_kernel<<<dim3(cfg::DC / 32, cfg::DC / 32), 256>>>(
        Wk, (__half2*)Wkvt, cfg::DC, cfg::DC);
    transpose16_kernel<<<dim3(cfg::DC / 32, cfg::DC / 32), 256>>>(
        Wv, (__half2*)(Wkvt + (size_t)cfg::DC * cfg::DC), cfg::DC, cfg::DC);
    transpose16_kernel<<<dim3(cfg::DFF / 32, cfg::DC / 32), 256>>>(
        W1, (__half2*)W1t, cfg::DC, cfg::DFF);
    transpose16_kernel<<<dim3(cfg::DC / 32, cfg::DFF / 32), 256>>>(
        W2, (__half2*)W2t, cfg::DFF, cfg::DC);
    nk16_kernel<<<1, 256>>>(nullk, (__half2*)nk16);

    ln_kernel<<<cfg::MR, 256>>>(X, g0, b0, (__half2*)Xn);
    ln_kernel<<<cfg::MR, 256>>>(Y, g0kv, b0kv, (__half2*)Yn);

    gemm_h<1, false><<<dim3(cfg::DC / 128, cfg::MR / 128), 256, gemm_smem>>>(
        Xn, Wqt, bq, bq, 1 << 30, Q16, nullptr, cfg::MR, cfg::DC, cfg::DC);
    gemm_h<1, false><<<dim3(2 * cfg::DC / 128, cfg::MR / 128), 256, gemm_smem>>>(
        Yn, Wkvt, bk, bv, cfg::DC, KV16, nullptr, cfg::MR, 2 * cfg::DC, cfg::DC);

    attn_kernel<<<dim3(cfg::NQC / 128, 16, cfg::BB), 256, attn_smem>>>(
        Q16, KV16, nk16, zero16, X, Hres);

    ln_kernel<<<cfg::MR, 256>>>(Hres, g1, b1, (__half2*)Hr);

    gemm_h<2, false><<<dim3(cfg::DFF / 128, cfg::MR / 128), 256, gemm_smem>>>(
        Hr, W1t, bf1, bf1, 1 << 30, Hid, nullptr, cfg::MR, cfg::DFF, cfg::DC);
    gemm_h<0, true><<<dim3(cfg::DC / 128, cfg::MR / 128), 256, gemm_smem>>>(
        Hid, W2t, bf2, bf2, 1 << 30, out, Hres, cfg::MR, cfg::DC, cfg::DFF);
}